// round 3
// baseline (speedup 1.0000x reference)
#include <cuda_runtime.h>
#include <math.h>

#define BATCH 4096
#define NDENSE 13
#define NTAB 26
#define VOCAB 100000
#define EMBD 64
#define NT1 27            // tables + 1
#define NPAIR 351         // 27*26/2
#define RDIM 415          // 64 + 351

// Intermediates (allocation-free scratch)
__device__ float g_x1[BATCH * 512];
__device__ float g_x2[BATCH * 256];
__device__ float g_x3[BATCH * 64];
__device__ float g_R [BATCH * RDIM];
__device__ float g_z1[BATCH * 512];
__device__ float g_z2[BATCH * 256];

// ---------------------------------------------------------------------------
// C[m][n] = act( sum_k A[m*lda+k] * W[n*ldw+k] + bias[n] ), NT layout.
// BM=128, BN=64, BK=16, 256 threads, 8x4 microtile.
// M multiple of 128, N multiple of 64, K arbitrary (guarded).
// ---------------------------------------------------------------------------
__global__ __launch_bounds__(256)
void gemm_nt_bias_relu(const float* __restrict__ A,
                       const float* __restrict__ W,
                       const float* __restrict__ bias,
                       float* __restrict__ C,
                       int K, int lda, int ldw, int ldc, int do_relu)
{
    __shared__ float As[16][129];
    __shared__ float Ws[16][65];

    const int tid = threadIdx.x;          // 0..255
    const int tx  = tid & 15;             // 16 cols of n
    const int ty  = tid >> 4;             // 16 rows of m
    const int bm  = blockIdx.y * 128;
    const int bn  = blockIdx.x * 64;

    float c[8][4] = {};

    for (int k0 = 0; k0 < K; k0 += 16) {
        // load A tile: 128x16 = 2048 elems, 8 per thread
        #pragma unroll
        for (int r = 0; r < 8; r++) {
            int idx = tid + r * 256;
            int m   = idx >> 4;
            int k   = idx & 15;
            float v = 0.f;
            if (k0 + k < K) v = A[(size_t)(bm + m) * lda + k0 + k];
            As[k][m] = v;
        }
        // load W tile: 64x16 = 1024 elems, 4 per thread
        #pragma unroll
        for (int r = 0; r < 4; r++) {
            int idx = tid + r * 256;
            int m   = idx >> 4;
            int k   = idx & 15;
            float v = 0.f;
            if (k0 + k < K) v = W[(size_t)(bn + m) * ldw + k0 + k];
            Ws[k][m] = v;
        }
        __syncthreads();

        #pragma unroll
        for (int k = 0; k < 16; k++) {
            float a[8], w[4];
            #pragma unroll
            for (int i = 0; i < 8; i++) a[i] = As[k][ty + i * 16];
            #pragma unroll
            for (int j = 0; j < 4; j++) w[j] = Ws[k][tx + j * 16];
            #pragma unroll
            for (int i = 0; i < 8; i++)
                #pragma unroll
                for (int j = 0; j < 4; j++)
                    c[i][j] = fmaf(a[i], w[j], c[i][j]);
        }
        __syncthreads();
    }

    #pragma unroll
    for (int i = 0; i < 8; i++) {
        int m = bm + ty + i * 16;
        #pragma unroll
        for (int j = 0; j < 4; j++) {
            int n = bn + tx + j * 16;
            float v = c[i][j] + bias[n];
            if (do_relu) v = fmaxf(v, 0.f);
            C[(size_t)m * ldc + n] = v;
        }
    }
}

// ---------------------------------------------------------------------------
// Fused embedding-gather + interaction. One 256-thread block per batch row.
// Gathers 26 bag-sums + x row into smem, computes 351 pairwise dots,
// writes R[b] = [ x(64) | Zflat(351) ].
// ---------------------------------------------------------------------------
__global__ __launch_bounds__(256)
void gather_interact(const int* __restrict__ lS_o,
                     const int* __restrict__ lS_i,
                     const float* __restrict__ emb)
{
    __shared__ float Ts[NT1 * 65]; // padded rows -> conflict-free

    const int b   = blockIdx.x;
    const int tid = threadIdx.x;   // 0..255

    // row 0 = x from bottom MLP
    if (tid < EMBD) Ts[tid] = g_x3[(size_t)b * EMBD + tid];

    // rows 1..26 = embedding bag sums (coalesced per row, ~7 rows in flight)
    for (int idx = tid; idx < NTAB * EMBD; idx += 256) {
        int t = idx >> 6;
        int d = idx & 63;
        int start = lS_o[t * BATCH + b];
        int end   = (b + 1 < BATCH) ? lS_o[t * BATCH + b + 1] : BATCH;
        const float* tab = emb + (size_t)t * VOCAB * EMBD;
        float s = 0.f;
        for (int p = start; p < end; p++) {
            int i = lS_i[t * BATCH + p];
            s += tab[(size_t)i * EMBD + d];
        }
        Ts[(t + 1) * 65 + d] = s;
    }
    __syncthreads();

    float* Rb = g_R + (size_t)b * RDIM;
    if (tid < EMBD) Rb[tid] = Ts[tid];

    for (int p = tid; p < NPAIR; p += 256) {
        int i = (int)floorf((sqrtf(8.f * (float)p + 1.f) + 1.f) * 0.5f);
        while (i * (i - 1) / 2 > p) i--;
        while ((i + 1) * i / 2 <= p) i++;
        int j = p - i * (i - 1) / 2;

        const float* ri = &Ts[i * 65];
        const float* rj = &Ts[j * 65];
        float s = 0.f;
        #pragma unroll
        for (int d = 0; d < 64; d++) s = fmaf(ri[d], rj[d], s);
        Rb[64 + p] = s;
    }
}

// ---------------------------------------------------------------------------
// Final layer: out[b] = sigmoid( dot(z2[b], tw2) + tb2 ). One warp per row.
// ---------------------------------------------------------------------------
__global__ __launch_bounds__(256)
void top_final(const float* __restrict__ w,
               const float* __restrict__ bias,
               float* __restrict__ out)
{
    int gwarp = (blockIdx.x * blockDim.x + threadIdx.x) >> 5;
    int lane  = threadIdx.x & 31;
    if (gwarp >= BATCH) return;

    const float* z = g_z2 + (size_t)gwarp * 256;
    float s = 0.f;
    #pragma unroll
    for (int k = lane; k < 256; k += 32) s = fmaf(z[k], w[k], s);
    #pragma unroll
    for (int o = 16; o; o >>= 1) s += __shfl_xor_sync(0xFFFFFFFFu, s, o);
    if (lane == 0) out[gwarp] = 1.f / (1.f + expf(-(s + bias[0])));
}

// ---------------------------------------------------------------------------
extern "C" void kernel_launch(void* const* d_in, const int* in_sizes, int n_in,
                              void* d_out, int out_size)
{
    const float* dense_x = (const float*)d_in[0];
    const int*   lS_o    = (const int*)  d_in[1];
    const int*   lS_i    = (const int*)  d_in[2];
    const float* emb     = (const float*)d_in[3];
    const float* bw0     = (const float*)d_in[4];
    const float* bb0     = (const float*)d_in[5];
    const float* bw1     = (const float*)d_in[6];
    const float* bb1     = (const float*)d_in[7];
    const float* bw2     = (const float*)d_in[8];
    const float* bb2     = (const float*)d_in[9];
    const float* tw0     = (const float*)d_in[10];
    const float* tb0     = (const float*)d_in[11];
    const float* tw1     = (const float*)d_in[12];
    const float* tb1     = (const float*)d_in[13];
    const float* tw2     = (const float*)d_in[14];
    const float* tb2     = (const float*)d_in[15];
    float* out = (float*)d_out;

    float *x1, *x2, *x3, *R, *z1, *z2;
    cudaGetSymbolAddress((void**)&x1, g_x1);
    cudaGetSymbolAddress((void**)&x2, g_x2);
    cudaGetSymbolAddress((void**)&x3, g_x3);
    cudaGetSymbolAddress((void**)&R,  g_R);
    cudaGetSymbolAddress((void**)&z1, g_z1);
    cudaGetSymbolAddress((void**)&z2, g_z2);

    // Bottom MLP
    gemm_nt_bias_relu<<<dim3(512 / 64, BATCH / 128), 256>>>(dense_x, bw0, bb0, x1,
                                                            13, 13, 13, 512, 1);
    gemm_nt_bias_relu<<<dim3(256 / 64, BATCH / 128), 256>>>(x1, bw1, bb1, x2,
                                                            512, 512, 512, 256, 1);
    gemm_nt_bias_relu<<<dim3(64 / 64, BATCH / 128), 256>>>(x2, bw2, bb2, x3,
                                                           256, 256, 256, 64, 1);

    // Fused gather + interaction -> R
    gather_interact<<<BATCH, 256>>>(lS_o, lS_i, emb);

    // Top MLP
    gemm_nt_bias_relu<<<dim3(512 / 64, BATCH / 128), 256>>>(R, tw0, tb0, z1,
                                                            RDIM, RDIM, RDIM, 512, 1);
    gemm_nt_bias_relu<<<dim3(256 / 64, BATCH / 128), 256>>>(z1, tw1, tb1, z2,
                                                            512, 512, 512, 256, 1);
    top_final<<<(BATCH * 32 + 255) / 256, 256>>>(tw2, tb2, out);
}

// round 4
// speedup vs baseline: 2.1126x; 2.1126x over previous
#include <cuda_runtime.h>
#include <cuda_bf16.h>
#include <math.h>
#include <stdint.h>

#define BATCH 4096
#define NDENSE 13
#define NTAB 26
#define VOCAB 100000
#define EMBD 64
#define NT1 27            // tables + 1
#define NPAIR 351         // 27*26/2
#define RDIM 415          // 64 + 351

// Intermediates (allocation-free scratch)
__device__ float g_x1[BATCH * 512];
__device__ float g_x2[BATCH * 256];
__device__ float g_x3[BATCH * 64];
__device__ float g_R [BATCH * RDIM];
__device__ float g_z1[BATCH * 512];
__device__ float g_z2[BATCH * 256];

__device__ __forceinline__ uint32_t pack_bf16x2(float lo, float hi)
{
    __nv_bfloat162 p = __floats2bfloat162_rn(lo, hi); // .x = lo half (first elem)
    return *reinterpret_cast<uint32_t*>(&p);
}

__device__ __forceinline__ void mma_bf16(float* c, const uint32_t* a, const uint32_t* b)
{
    asm volatile(
        "mma.sync.aligned.m16n8k16.row.col.f32.bf16.bf16.f32 "
        "{%0,%1,%2,%3}, {%4,%5,%6,%7}, {%8,%9}, {%0,%1,%2,%3};"
        : "+f"(c[0]), "+f"(c[1]), "+f"(c[2]), "+f"(c[3])
        : "r"(a[0]), "r"(a[1]), "r"(a[2]), "r"(a[3]), "r"(b[0]), "r"(b[1]));
}

// ---------------------------------------------------------------------------
// C[m][n] = act( sum_k A[m*lda+k] * W[n*ldw+k] + bias[n] )  (NT layout)
// Tensor-core path: fp32 inputs split into bf16 hi/lo, 3-pass accumulation
// (hh + hl + lh) in fp32 => ~1e-5 relative accuracy.
// BM=128, BN=64, BK=16(fp32), 256 threads, 8 warps in a 4(m) x 2(n) grid,
// each warp computes 32x32 via 2x4 m16n8k16 tiles.
// M % 128 == 0, N % 64 == 0, K arbitrary (zero-padded).
// ---------------------------------------------------------------------------
__global__ __launch_bounds__(256)
void gemm_nt_mma(const float* __restrict__ A,
                 const float* __restrict__ W,
                 const float* __restrict__ bias,
                 float* __restrict__ C,
                 int K, int lda, int ldw, int ldc, int do_relu)
{
    // XOR-swizzled smem, unit = u32 (one bf16x2 k-pair). 8 pairs per row.
    __shared__ uint32_t sHA[128 * 8];
    __shared__ uint32_t sLA[128 * 8];
    __shared__ uint32_t sHW[64 * 8];
    __shared__ uint32_t sLW[64 * 8];

    const int tid  = threadIdx.x;
    const int lane = tid & 31;
    const int wid  = tid >> 5;
    const int wm   = wid & 3;      // warp row (4 x 32 = 128)
    const int wn   = wid >> 2;     // warp col (2 x 32 = 64)
    const int g    = lane >> 2;    // group id 0..7
    const int tg   = lane & 3;     // thread-in-group 0..3
    const int bm   = blockIdx.y * 128;
    const int bn   = blockIdx.x * 64;

    const int pr   = tid & 7;      // pair index 0..7 (k = 2*pr, 2*pr+1)
    const int row0 = tid >> 3;     // 0..31

    float acc[2][4][4];
    #pragma unroll
    for (int i = 0; i < 2; i++)
        #pragma unroll
        for (int j = 0; j < 4; j++)
            #pragma unroll
            for (int q = 0; q < 4; q++) acc[i][j][q] = 0.f;

    for (int k0 = 0; k0 < K; k0 += 16) {
        // ---- load + split A tile (128 x 16 fp32) ----
        #pragma unroll
        for (int r = 0; r < 4; r++) {
            int m  = row0 + r * 32;
            int kk = k0 + pr * 2;
            const float* ap = A + (size_t)(bm + m) * lda;
            float v0 = (kk     < K) ? __ldg(ap + kk)     : 0.f;
            float v1 = (kk + 1 < K) ? __ldg(ap + kk + 1) : 0.f;
            float h0 = __bfloat162float(__float2bfloat16(v0));
            float h1 = __bfloat162float(__float2bfloat16(v1));
            int idx = m * 8 + (pr ^ (m & 7));
            sHA[idx] = pack_bf16x2(h0, h1);
            sLA[idx] = pack_bf16x2(v0 - h0, v1 - h1);
        }
        // ---- load + split W tile (64 x 16 fp32) ----
        #pragma unroll
        for (int r = 0; r < 2; r++) {
            int n  = row0 + r * 32;
            int kk = k0 + pr * 2;
            const float* wp = W + (size_t)(bn + n) * ldw;
            float v0 = (kk     < K) ? __ldg(wp + kk)     : 0.f;
            float v1 = (kk + 1 < K) ? __ldg(wp + kk + 1) : 0.f;
            float h0 = __bfloat162float(__float2bfloat16(v0));
            float h1 = __bfloat162float(__float2bfloat16(v1));
            int idx = n * 8 + (pr ^ (n & 7));
            sHW[idx] = pack_bf16x2(h0, h1);
            sLW[idx] = pack_bf16x2(v0 - h0, v1 - h1);
        }
        __syncthreads();

        // ---- fragment loads ----
        uint32_t ah[2][4], al[2][4], bh[4][2], bl[4][2];
        #pragma unroll
        for (int mt = 0; mt < 2; mt++) {
            int r0 = wm * 32 + mt * 16 + g;
            int r1 = r0 + 8;
            int s0 = r0 & 7, s1 = r1 & 7;
            ah[mt][0] = sHA[r0 * 8 + (tg ^ s0)];
            ah[mt][1] = sHA[r1 * 8 + (tg ^ s1)];
            ah[mt][2] = sHA[r0 * 8 + ((tg + 4) ^ s0)];
            ah[mt][3] = sHA[r1 * 8 + ((tg + 4) ^ s1)];
            al[mt][0] = sLA[r0 * 8 + (tg ^ s0)];
            al[mt][1] = sLA[r1 * 8 + (tg ^ s1)];
            al[mt][2] = sLA[r0 * 8 + ((tg + 4) ^ s0)];
            al[mt][3] = sLA[r1 * 8 + ((tg + 4) ^ s1)];
        }
        #pragma unroll
        for (int nt = 0; nt < 4; nt++) {
            int nb = wn * 32 + nt * 8 + g;
            int sn = nb & 7;
            bh[nt][0] = sHW[nb * 8 + (tg ^ sn)];
            bh[nt][1] = sHW[nb * 8 + ((tg + 4) ^ sn)];
            bl[nt][0] = sLW[nb * 8 + (tg ^ sn)];
            bl[nt][1] = sLW[nb * 8 + ((tg + 4) ^ sn)];
        }

        // ---- 3-pass MMA: hh + hl + lh ----
        #pragma unroll
        for (int mt = 0; mt < 2; mt++)
            #pragma unroll
            for (int nt = 0; nt < 4; nt++) {
                mma_bf16(acc[mt][nt], ah[mt], bh[nt]);
                mma_bf16(acc[mt][nt], ah[mt], bl[nt]);
                mma_bf16(acc[mt][nt], al[mt], bh[nt]);
            }
        __syncthreads();
    }

    // ---- epilogue: bias + activation ----
    #pragma unroll
    for (int mt = 0; mt < 2; mt++) {
        int r0 = bm + wm * 32 + mt * 16 + g;
        #pragma unroll
        for (int nt = 0; nt < 4; nt++) {
            int col = bn + wn * 32 + nt * 8 + tg * 2;
            float bi0 = bias[col], bi1 = bias[col + 1];
            float v0 = acc[mt][nt][0] + bi0;
            float v1 = acc[mt][nt][1] + bi1;
            float v2 = acc[mt][nt][2] + bi0;
            float v3 = acc[mt][nt][3] + bi1;
            if (do_relu) {
                v0 = fmaxf(v0, 0.f); v1 = fmaxf(v1, 0.f);
                v2 = fmaxf(v2, 0.f); v3 = fmaxf(v3, 0.f);
            }
            C[(size_t)r0 * ldc + col]           = v0;
            C[(size_t)r0 * ldc + col + 1]       = v1;
            C[(size_t)(r0 + 8) * ldc + col]     = v2;
            C[(size_t)(r0 + 8) * ldc + col + 1] = v3;
        }
    }
}

// ---------------------------------------------------------------------------
// Fused embedding-gather + interaction. One 256-thread block per batch row.
// ---------------------------------------------------------------------------
__global__ __launch_bounds__(256)
void gather_interact(const int* __restrict__ lS_o,
                     const int* __restrict__ lS_i,
                     const float* __restrict__ emb)
{
    __shared__ float Ts[NT1 * 65]; // padded rows -> conflict-free

    const int b   = blockIdx.x;
    const int tid = threadIdx.x;   // 0..255

    // row 0 = x from bottom MLP
    if (tid < EMBD) Ts[tid] = g_x3[(size_t)b * EMBD + tid];

    // rows 1..26 = embedding bag sums
    for (int idx = tid; idx < NTAB * EMBD; idx += 256) {
        int t = idx >> 6;
        int d = idx & 63;
        int start = lS_o[t * BATCH + b];
        int end   = (b + 1 < BATCH) ? lS_o[t * BATCH + b + 1] : BATCH;
        const float* tab = emb + (size_t)t * VOCAB * EMBD;
        float s = 0.f;
        for (int p = start; p < end; p++) {
            int i = lS_i[t * BATCH + p];
            s += tab[(size_t)i * EMBD + d];
        }
        Ts[(t + 1) * 65 + d] = s;
    }
    __syncthreads();

    float* Rb = g_R + (size_t)b * RDIM;
    if (tid < EMBD) Rb[tid] = Ts[tid];

    for (int p = tid; p < NPAIR; p += 256) {
        int i = (int)floorf((sqrtf(8.f * (float)p + 1.f) + 1.f) * 0.5f);
        while (i * (i - 1) / 2 > p) i--;
        while ((i + 1) * i / 2 <= p) i++;
        int j = p - i * (i - 1) / 2;

        const float* ri = &Ts[i * 65];
        const float* rj = &Ts[j * 65];
        float s = 0.f;
        #pragma unroll
        for (int d = 0; d < 64; d++) s = fmaf(ri[d], rj[d], s);
        Rb[64 + p] = s;
    }
}

// ---------------------------------------------------------------------------
// Final layer: out[b] = sigmoid( dot(z2[b], tw2) + tb2 ). One warp per row.
// ---------------------------------------------------------------------------
__global__ __launch_bounds__(256)
void top_final(const float* __restrict__ w,
               const float* __restrict__ bias,
               float* __restrict__ out)
{
    int gwarp = (blockIdx.x * blockDim.x + threadIdx.x) >> 5;
    int lane  = threadIdx.x & 31;
    if (gwarp >= BATCH) return;

    const float* z = g_z2 + (size_t)gwarp * 256;
    float s = 0.f;
    #pragma unroll
    for (int k = lane; k < 256; k += 32) s = fmaf(z[k], w[k], s);
    #pragma unroll
    for (int o = 16; o; o >>= 1) s += __shfl_xor_sync(0xFFFFFFFFu, s, o);
    if (lane == 0) out[gwarp] = 1.f / (1.f + expf(-(s + bias[0])));
}

// ---------------------------------------------------------------------------
extern "C" void kernel_launch(void* const* d_in, const int* in_sizes, int n_in,
                              void* d_out, int out_size)
{
    const float* dense_x = (const float*)d_in[0];
    const int*   lS_o    = (const int*)  d_in[1];
    const int*   lS_i    = (const int*)  d_in[2];
    const float* emb     = (const float*)d_in[3];
    const float* bw0     = (const float*)d_in[4];
    const float* bb0     = (const float*)d_in[5];
    const float* bw1     = (const float*)d_in[6];
    const float* bb1     = (const float*)d_in[7];
    const float* bw2     = (const float*)d_in[8];
    const float* bb2     = (const float*)d_in[9];
    const float* tw0     = (const float*)d_in[10];
    const float* tb0     = (const float*)d_in[11];
    const float* tw1     = (const float*)d_in[12];
    const float* tb1     = (const float*)d_in[13];
    const float* tw2     = (const float*)d_in[14];
    const float* tb2     = (const float*)d_in[15];
    float* out = (float*)d_out;

    float *x1, *x2, *x3, *R, *z1, *z2;
    cudaGetSymbolAddress((void**)&x1, g_x1);
    cudaGetSymbolAddress((void**)&x2, g_x2);
    cudaGetSymbolAddress((void**)&x3, g_x3);
    cudaGetSymbolAddress((void**)&R,  g_R);
    cudaGetSymbolAddress((void**)&z1, g_z1);
    cudaGetSymbolAddress((void**)&z2, g_z2);

    // Bottom MLP (tensor cores)
    gemm_nt_mma<<<dim3(512 / 64, BATCH / 128), 256>>>(dense_x, bw0, bb0, x1,
                                                      13, 13, 13, 512, 1);
    gemm_nt_mma<<<dim3(256 / 64, BATCH / 128), 256>>>(x1, bw1, bb1, x2,
                                                      512, 512, 512, 256, 1);
    gemm_nt_mma<<<dim3(64 / 64, BATCH / 128), 256>>>(x2, bw2, bb2, x3,
                                                     256, 256, 256, 64, 1);

    // Fused gather + interaction -> R
    gather_interact<<<BATCH, 256>>>(lS_o, lS_i, emb);

    // Top MLP (tensor cores)
    gemm_nt_mma<<<dim3(512 / 64, BATCH / 128), 256>>>(R, tw0, tb0, z1,
                                                      RDIM, RDIM, RDIM, 512, 1);
    gemm_nt_mma<<<dim3(256 / 64, BATCH / 128), 256>>>(z1, tw1, tb1, z2,
                                                      512, 512, 512, 256, 1);
    top_final<<<(BATCH * 32 + 255) / 256, 256>>>(tw2, tb2, out);
}

// round 5
// speedup vs baseline: 2.5282x; 1.1967x over previous
#include <cuda_runtime.h>
#include <cuda_bf16.h>
#include <math.h>
#include <stdint.h>

#define BATCH 4096
#define NDENSE 13
#define NTAB 26
#define VOCAB 100000
#define EMBD 64
#define NT1 27            // tables + 1
#define NPAIR 351         // 27*26/2
#define RDIM 415          // 64 + 351
#define TSTRIDE 68        // floats per T row in smem (16B aligned, bank-skewed)

// Intermediates (allocation-free scratch)
__device__ float g_x1[BATCH * 512];
__device__ float g_x2[BATCH * 256];
__device__ float g_x3[BATCH * 64];
__device__ float g_R [BATCH * RDIM];
__device__ float g_z1[BATCH * 512];
__device__ float g_z2[BATCH * 256];

__device__ __forceinline__ uint32_t pack_bf16x2(float lo, float hi)
{
    __nv_bfloat162 p = __floats2bfloat162_rn(lo, hi);
    return *reinterpret_cast<uint32_t*>(&p);
}

__device__ __forceinline__ void mma_bf16(float* c, const uint32_t* a, const uint32_t* b)
{
    asm volatile(
        "mma.sync.aligned.m16n8k16.row.col.f32.bf16.bf16.f32 "
        "{%0,%1,%2,%3}, {%4,%5,%6,%7}, {%8,%9}, {%0,%1,%2,%3};"
        : "+f"(c[0]), "+f"(c[1]), "+f"(c[2]), "+f"(c[3])
        : "r"(a[0]), "r"(a[1]), "r"(a[2]), "r"(a[3]), "r"(b[0]), "r"(b[1]));
}

// ---------------------------------------------------------------------------
// C[m][n] = act( sum_k A[m*lda+k] * W[n*ldw+k] + bias[n] )  (NT layout)
// bf16 hi/lo split, 3-pass (hh+hl+lh) fp32 accumulation (~1e-7 accuracy).
// BM=128, BN=64, BK=16, 256 threads, 8 warps (4m x 2n), warp tile 32x32.
// Register-prefetch software pipeline on the K loop.
// ---------------------------------------------------------------------------
__global__ __launch_bounds__(256)
void gemm_nt_mma(const float* __restrict__ A,
                 const float* __restrict__ W,
                 const float* __restrict__ bias,
                 float* __restrict__ C,
                 int K, int lda, int ldw, int ldc, int do_relu)
{
    __shared__ uint32_t sHA[128 * 8];
    __shared__ uint32_t sLA[128 * 8];
    __shared__ uint32_t sHW[64 * 8];
    __shared__ uint32_t sLW[64 * 8];

    const int tid  = threadIdx.x;
    const int lane = tid & 31;
    const int wid  = tid >> 5;
    const int wm   = wid & 3;
    const int wn   = wid >> 2;
    const int g    = lane >> 2;
    const int tg   = lane & 3;
    const int bm   = blockIdx.y * 128;
    const int bn   = blockIdx.x * 64;

    const int pr   = tid & 7;      // k-pair index 0..7
    const int row0 = tid >> 3;     // 0..31

    float acc[2][4][4];
    #pragma unroll
    for (int i = 0; i < 2; i++)
        #pragma unroll
        for (int j = 0; j < 4; j++)
            #pragma unroll
            for (int q = 0; q < 4; q++) acc[i][j][q] = 0.f;

    float pa[4][2], pw[2][2];

    // prefetch tile 0
    {
        int kk = pr * 2;
        #pragma unroll
        for (int r = 0; r < 4; r++) {
            const float* ap = A + (size_t)(bm + row0 + r * 32) * lda;
            pa[r][0] = (kk     < K) ? __ldg(ap + kk)     : 0.f;
            pa[r][1] = (kk + 1 < K) ? __ldg(ap + kk + 1) : 0.f;
        }
        #pragma unroll
        for (int r = 0; r < 2; r++) {
            const float* wp = W + (size_t)(bn + row0 + r * 32) * ldw;
            pw[r][0] = (kk     < K) ? __ldg(wp + kk)     : 0.f;
            pw[r][1] = (kk + 1 < K) ? __ldg(wp + kk + 1) : 0.f;
        }
    }

    for (int k0 = 0; k0 < K; k0 += 16) {
        // ---- split + store current tile ----
        #pragma unroll
        for (int r = 0; r < 4; r++) {
            int m = row0 + r * 32;
            float h0 = __bfloat162float(__float2bfloat16(pa[r][0]));
            float h1 = __bfloat162float(__float2bfloat16(pa[r][1]));
            int idx = m * 8 + (pr ^ (m & 7));
            sHA[idx] = pack_bf16x2(h0, h1);
            sLA[idx] = pack_bf16x2(pa[r][0] - h0, pa[r][1] - h1);
        }
        #pragma unroll
        for (int r = 0; r < 2; r++) {
            int n = row0 + r * 32;
            float h0 = __bfloat162float(__float2bfloat16(pw[r][0]));
            float h1 = __bfloat162float(__float2bfloat16(pw[r][1]));
            int idx = n * 8 + (pr ^ (n & 7));
            sHW[idx] = pack_bf16x2(h0, h1);
            sLW[idx] = pack_bf16x2(pw[r][0] - h0, pw[r][1] - h1);
        }
        __syncthreads();

        // ---- prefetch next tile (overlaps with MMA below) ----
        if (k0 + 16 < K) {
            int kk = k0 + 16 + pr * 2;
            #pragma unroll
            for (int r = 0; r < 4; r++) {
                const float* ap = A + (size_t)(bm + row0 + r * 32) * lda;
                pa[r][0] = (kk     < K) ? __ldg(ap + kk)     : 0.f;
                pa[r][1] = (kk + 1 < K) ? __ldg(ap + kk + 1) : 0.f;
            }
            #pragma unroll
            for (int r = 0; r < 2; r++) {
                const float* wp = W + (size_t)(bn + row0 + r * 32) * ldw;
                pw[r][0] = (kk     < K) ? __ldg(wp + kk)     : 0.f;
                pw[r][1] = (kk + 1 < K) ? __ldg(wp + kk + 1) : 0.f;
            }
        }

        // ---- fragment loads ----
        uint32_t ah[2][4], al[2][4], bh[4][2], bl[4][2];
        #pragma unroll
        for (int mt = 0; mt < 2; mt++) {
            int r0 = wm * 32 + mt * 16 + g;
            int r1 = r0 + 8;
            int s0 = r0 & 7, s1 = r1 & 7;
            ah[mt][0] = sHA[r0 * 8 + (tg ^ s0)];
            ah[mt][1] = sHA[r1 * 8 + (tg ^ s1)];
            ah[mt][2] = sHA[r0 * 8 + ((tg + 4) ^ s0)];
            ah[mt][3] = sHA[r1 * 8 + ((tg + 4) ^ s1)];
            al[mt][0] = sLA[r0 * 8 + (tg ^ s0)];
            al[mt][1] = sLA[r1 * 8 + (tg ^ s1)];
            al[mt][2] = sLA[r0 * 8 + ((tg + 4) ^ s0)];
            al[mt][3] = sLA[r1 * 8 + ((tg + 4) ^ s1)];
        }
        #pragma unroll
        for (int nt = 0; nt < 4; nt++) {
            int nb = wn * 32 + nt * 8 + g;
            int sn = nb & 7;
            bh[nt][0] = sHW[nb * 8 + (tg ^ sn)];
            bh[nt][1] = sHW[nb * 8 + ((tg + 4) ^ sn)];
            bl[nt][0] = sLW[nb * 8 + (tg ^ sn)];
            bl[nt][1] = sLW[nb * 8 + ((tg + 4) ^ sn)];
        }

        // ---- 3-pass MMA ----
        #pragma unroll
        for (int mt = 0; mt < 2; mt++)
            #pragma unroll
            for (int nt = 0; nt < 4; nt++) {
                mma_bf16(acc[mt][nt], ah[mt], bh[nt]);
                mma_bf16(acc[mt][nt], ah[mt], bl[nt]);
                mma_bf16(acc[mt][nt], al[mt], bh[nt]);
            }
        __syncthreads();
    }

    // ---- epilogue ----
    #pragma unroll
    for (int mt = 0; mt < 2; mt++) {
        int r0 = bm + wm * 32 + mt * 16 + g;
        #pragma unroll
        for (int nt = 0; nt < 4; nt++) {
            int col = bn + wn * 32 + nt * 8 + tg * 2;
            float bi0 = bias[col], bi1 = bias[col + 1];
            float v0 = acc[mt][nt][0] + bi0;
            float v1 = acc[mt][nt][1] + bi1;
            float v2 = acc[mt][nt][2] + bi0;
            float v3 = acc[mt][nt][3] + bi1;
            if (do_relu) {
                v0 = fmaxf(v0, 0.f); v1 = fmaxf(v1, 0.f);
                v2 = fmaxf(v2, 0.f); v3 = fmaxf(v3, 0.f);
            }
            C[(size_t)r0 * ldc + col]           = v0;
            C[(size_t)r0 * ldc + col + 1]       = v1;
            C[(size_t)(r0 + 8) * ldc + col]     = v2;
            C[(size_t)(r0 + 8) * ldc + col + 1] = v3;
        }
    }
}

// ---------------------------------------------------------------------------
// Fused embedding-gather + interaction, v2.
// One 256-thread block per batch row. Offsets staged in smem; gather as
// 416 (table, float4-quad) tasks; interaction dots via float4 smem loads.
// ---------------------------------------------------------------------------
__global__ __launch_bounds__(256)
void gather_interact(const int* __restrict__ lS_o,
                     const int* __restrict__ lS_i,
                     const float* __restrict__ emb)
{
    __shared__ float Ts[NT1 * TSTRIDE];
    __shared__ int s_beg[NTAB];
    __shared__ int s_end[NTAB];

    const int b   = blockIdx.x;
    const int tid = threadIdx.x;

    if (tid < NTAB) {
        s_beg[tid] = lS_o[tid * BATCH + b];
        s_end[tid] = (b + 1 < BATCH) ? lS_o[tid * BATCH + b + 1] : BATCH;
    }
    // row 0 = x from bottom MLP (16 float4)
    if (tid < 16) {
        float4 v = reinterpret_cast<const float4*>(g_x3 + (size_t)b * EMBD)[tid];
        *reinterpret_cast<float4*>(&Ts[tid * 4]) = v;
    }
    __syncthreads();

    // 26 tables x 16 quads = 416 tasks
    for (int task = tid; task < NTAB * 16; task += 256) {
        int t = task >> 4;
        int q = task & 15;
        const float* tab = emb + (size_t)t * VOCAB * EMBD + q * 4;
        float4 acc = make_float4(0.f, 0.f, 0.f, 0.f);
        int e = s_end[t];
        for (int p = s_beg[t]; p < e; p++) {
            int i = lS_i[t * BATCH + p];
            float4 v = *reinterpret_cast<const float4*>(tab + (size_t)i * EMBD);
            acc.x += v.x; acc.y += v.y; acc.z += v.z; acc.w += v.w;
        }
        *reinterpret_cast<float4*>(&Ts[(t + 1) * TSTRIDE + q * 4]) = acc;
    }
    __syncthreads();

    float* Rb = g_R + (size_t)b * RDIM;
    if (tid < EMBD) Rb[tid] = Ts[tid];

    for (int p = tid; p < NPAIR; p += 256) {
        int i = (int)((sqrtf(8.f * (float)p + 1.f) + 1.f) * 0.5f);
        while (i * (i - 1) / 2 > p) i--;
        while ((i + 1) * i / 2 <= p) i++;
        int j = p - i * (i - 1) / 2;

        const float4* ri = reinterpret_cast<const float4*>(&Ts[i * TSTRIDE]);
        const float4* rj = reinterpret_cast<const float4*>(&Ts[j * TSTRIDE]);
        float s = 0.f;
        #pragma unroll
        for (int d = 0; d < 16; d++) {
            float4 a = ri[d], c = rj[d];
            s = fmaf(a.x, c.x, s);
            s = fmaf(a.y, c.y, s);
            s = fmaf(a.z, c.z, s);
            s = fmaf(a.w, c.w, s);
        }
        Rb[64 + p] = s;
    }
}

// ---------------------------------------------------------------------------
// Final layer: out[b] = sigmoid( dot(z2[b], tw2) + tb2 ). One warp per row.
// ---------------------------------------------------------------------------
__global__ __launch_bounds__(256)
void top_final(const float* __restrict__ w,
               const float* __restrict__ bias,
               float* __restrict__ out)
{
    int gwarp = (blockIdx.x * blockDim.x + threadIdx.x) >> 5;
    int lane  = threadIdx.x & 31;
    if (gwarp >= BATCH) return;

    const float* z = g_z2 + (size_t)gwarp * 256;
    float s = 0.f;
    #pragma unroll
    for (int k = lane; k < 256; k += 32) s = fmaf(z[k], w[k], s);
    #pragma unroll
    for (int o = 16; o; o >>= 1) s += __shfl_xor_sync(0xFFFFFFFFu, s, o);
    if (lane == 0) out[gwarp] = 1.f / (1.f + expf(-(s + bias[0])));
}

// ---------------------------------------------------------------------------
extern "C" void kernel_launch(void* const* d_in, const int* in_sizes, int n_in,
                              void* d_out, int out_size)
{
    const float* dense_x = (const float*)d_in[0];
    const int*   lS_o    = (const int*)  d_in[1];
    const int*   lS_i    = (const int*)  d_in[2];
    const float* emb     = (const float*)d_in[3];
    const float* bw0     = (const float*)d_in[4];
    const float* bb0     = (const float*)d_in[5];
    const float* bw1     = (const float*)d_in[6];
    const float* bb1     = (const float*)d_in[7];
    const float* bw2     = (const float*)d_in[8];
    const float* bb2     = (const float*)d_in[9];
    const float* tw0     = (const float*)d_in[10];
    const float* tb0     = (const float*)d_in[11];
    const float* tw1     = (const float*)d_in[12];
    const float* tb1     = (const float*)d_in[13];
    const float* tw2     = (const float*)d_in[14];
    const float* tb2     = (const float*)d_in[15];
    float* out = (float*)d_out;

    float *x1, *x2, *x3, *R, *z1, *z2;
    cudaGetSymbolAddress((void**)&x1, g_x1);
    cudaGetSymbolAddress((void**)&x2, g_x2);
    cudaGetSymbolAddress((void**)&x3, g_x3);
    cudaGetSymbolAddress((void**)&R,  g_R);
    cudaGetSymbolAddress((void**)&z1, g_z1);
    cudaGetSymbolAddress((void**)&z2, g_z2);

    // Bottom MLP (tensor cores)
    gemm_nt_mma<<<dim3(512 / 64, BATCH / 128), 256>>>(dense_x, bw0, bb0, x1,
                                                      13, 13, 13, 512, 1);
    gemm_nt_mma<<<dim3(256 / 64, BATCH / 128), 256>>>(x1, bw1, bb1, x2,
                                                      512, 512, 512, 256, 1);
    gemm_nt_mma<<<dim3(64 / 64, BATCH / 128), 256>>>(x2, bw2, bb2, x3,
                                                     256, 256, 256, 64, 1);

    // Fused gather + interaction -> R
    gather_interact<<<BATCH, 256>>>(lS_o, lS_i, emb);

    // Top MLP (tensor cores)
    gemm_nt_mma<<<dim3(512 / 64, BATCH / 128), 256>>>(R, tw0, tb0, z1,
                                                      RDIM, RDIM, RDIM, 512, 1);
    gemm_nt_mma<<<dim3(256 / 64, BATCH / 128), 256>>>(z1, tw1, tb1, z2,
                                                      512, 512, 512, 256, 1);
    top_final<<<(BATCH * 32 + 255) / 256, 256>>>(tw2, tb2, out);
}

// round 6
// speedup vs baseline: 2.6157x; 1.0346x over previous
#include <cuda_runtime.h>
#include <cuda_bf16.h>
#include <math.h>
#include <stdint.h>

#define BATCH 4096
#define NDENSE 13
#define NTAB 26
#define VOCAB 100000
#define EMBD 64
#define NT1 27            // tables + 1
#define NPAIR 351         // 27*26/2
#define RDIM 415          // 64 + 351
#define SROW 33           // u32 stride of a T row in smem (32 bf16x2 pairs + pad)

// Intermediates (allocation-free scratch)
__device__ float g_x1[BATCH * 512];
__device__ float g_x2[BATCH * 256];
__device__ float g_x3[BATCH * 64];
__device__ float g_R [BATCH * RDIM];
__device__ float g_z1[BATCH * 512];
__device__ float g_z2[BATCH * 256];

__device__ __forceinline__ uint32_t pack_bf16x2(float lo, float hi)
{
    __nv_bfloat162 p = __floats2bfloat162_rn(lo, hi);
    return *reinterpret_cast<uint32_t*>(&p);
}

__device__ __forceinline__ float bf16_round(float v)
{
    return __bfloat162float(__float2bfloat16(v));
}

__device__ __forceinline__ void mma_bf16(float* c, const uint32_t* a, const uint32_t* b)
{
    asm volatile(
        "mma.sync.aligned.m16n8k16.row.col.f32.bf16.bf16.f32 "
        "{%0,%1,%2,%3}, {%4,%5,%6,%7}, {%8,%9}, {%0,%1,%2,%3};"
        : "+f"(c[0]), "+f"(c[1]), "+f"(c[2]), "+f"(c[3])
        : "r"(a[0]), "r"(a[1]), "r"(a[2]), "r"(a[3]), "r"(b[0]), "r"(b[1]));
}

// ---------------------------------------------------------------------------
// Templated NT GEMM on tensor cores: C = act(A @ W^T + bias).
// bf16 hi/lo split, 3-pass (hh+hl+lh) fp32 accumulation (~1e-7 accuracy).
// 256 threads = 8 warps arranged WM_ x WN_; warp tile (BM/WM_) x (BN/WN_).
// Register-prefetch pipeline on the K loop (BK = 16 fp32).
// ---------------------------------------------------------------------------
template<int BM, int BN, int WM_, int WN_>
__global__ __launch_bounds__(256)
void gemm_nt_mma(const float* __restrict__ A,
                 const float* __restrict__ W,
                 const float* __restrict__ bias,
                 float* __restrict__ C,
                 int K, int lda, int ldw, int ldc, int do_relu)
{
    constexpr int TM  = BM / WM_;   // warp tile rows (mult of 16)
    constexpr int TN  = BN / WN_;   // warp tile cols (mult of 8)
    constexpr int MT  = TM / 16;    // m16 tiles per warp
    constexpr int NTT = TN / 8;     // n8 tiles per warp
    constexpr int AR  = BM / 32;    // A rows per thread (global load)
    constexpr int WR  = BN / 32;    // W rows per thread

    __shared__ uint32_t sHA[BM * 8];
    __shared__ uint32_t sLA[BM * 8];
    __shared__ uint32_t sHW[BN * 8];
    __shared__ uint32_t sLW[BN * 8];

    const int tid  = threadIdx.x;
    const int lane = tid & 31;
    const int wid  = tid >> 5;
    const int wm   = wid % WM_;
    const int wn   = wid / WM_;
    const int g    = lane >> 2;
    const int tg   = lane & 3;
    const int bm   = blockIdx.y * BM;
    const int bn   = blockIdx.x * BN;

    const int pr   = tid & 7;      // k-pair index 0..7
    const int row0 = tid >> 3;     // 0..31

    float acc[MT][NTT][4];
    #pragma unroll
    for (int i = 0; i < MT; i++)
        #pragma unroll
        for (int j = 0; j < NTT; j++)
            #pragma unroll
            for (int q = 0; q < 4; q++) acc[i][j][q] = 0.f;

    float pa[AR][2], pw[WR][2];

    // prefetch tile 0
    {
        int kk = pr * 2;
        #pragma unroll
        for (int r = 0; r < AR; r++) {
            const float* ap = A + (size_t)(bm + row0 + r * 32) * lda;
            pa[r][0] = (kk     < K) ? __ldg(ap + kk)     : 0.f;
            pa[r][1] = (kk + 1 < K) ? __ldg(ap + kk + 1) : 0.f;
        }
        #pragma unroll
        for (int r = 0; r < WR; r++) {
            const float* wp = W + (size_t)(bn + row0 + r * 32) * ldw;
            pw[r][0] = (kk     < K) ? __ldg(wp + kk)     : 0.f;
            pw[r][1] = (kk + 1 < K) ? __ldg(wp + kk + 1) : 0.f;
        }
    }

    for (int k0 = 0; k0 < K; k0 += 16) {
        // ---- split + store current tile ----
        #pragma unroll
        for (int r = 0; r < AR; r++) {
            int m = row0 + r * 32;
            float h0 = bf16_round(pa[r][0]);
            float h1 = bf16_round(pa[r][1]);
            int idx = m * 8 + (pr ^ (m & 7));
            sHA[idx] = pack_bf16x2(h0, h1);
            sLA[idx] = pack_bf16x2(pa[r][0] - h0, pa[r][1] - h1);
        }
        #pragma unroll
        for (int r = 0; r < WR; r++) {
            int n = row0 + r * 32;
            float h0 = bf16_round(pw[r][0]);
            float h1 = bf16_round(pw[r][1]);
            int idx = n * 8 + (pr ^ (n & 7));
            sHW[idx] = pack_bf16x2(h0, h1);
            sLW[idx] = pack_bf16x2(pw[r][0] - h0, pw[r][1] - h1);
        }
        __syncthreads();

        // ---- prefetch next tile (overlaps with MMA below) ----
        if (k0 + 16 < K) {
            int kk = k0 + 16 + pr * 2;
            #pragma unroll
            for (int r = 0; r < AR; r++) {
                const float* ap = A + (size_t)(bm + row0 + r * 32) * lda;
                pa[r][0] = (kk     < K) ? __ldg(ap + kk)     : 0.f;
                pa[r][1] = (kk + 1 < K) ? __ldg(ap + kk + 1) : 0.f;
            }
            #pragma unroll
            for (int r = 0; r < WR; r++) {
                const float* wp = W + (size_t)(bn + row0 + r * 32) * ldw;
                pw[r][0] = (kk     < K) ? __ldg(wp + kk)     : 0.f;
                pw[r][1] = (kk + 1 < K) ? __ldg(wp + kk + 1) : 0.f;
            }
        }

        // ---- fragment loads ----
        uint32_t ah[MT][4], al[MT][4], bh[NTT][2], bl[NTT][2];
        #pragma unroll
        for (int mt = 0; mt < MT; mt++) {
            int r0 = wm * TM + mt * 16 + g;
            int r1 = r0 + 8;
            int s0 = r0 & 7, s1 = r1 & 7;
            ah[mt][0] = sHA[r0 * 8 + (tg ^ s0)];
            ah[mt][1] = sHA[r1 * 8 + (tg ^ s1)];
            ah[mt][2] = sHA[r0 * 8 + ((tg + 4) ^ s0)];
            ah[mt][3] = sHA[r1 * 8 + ((tg + 4) ^ s1)];
            al[mt][0] = sLA[r0 * 8 + (tg ^ s0)];
            al[mt][1] = sLA[r1 * 8 + (tg ^ s1)];
            al[mt][2] = sLA[r0 * 8 + ((tg + 4) ^ s0)];
            al[mt][3] = sLA[r1 * 8 + ((tg + 4) ^ s1)];
        }
        #pragma unroll
        for (int nt = 0; nt < NTT; nt++) {
            int nb = wn * TN + nt * 8 + g;
            int sn = nb & 7;
            bh[nt][0] = sHW[nb * 8 + (tg ^ sn)];
            bh[nt][1] = sHW[nb * 8 + ((tg + 4) ^ sn)];
            bl[nt][0] = sLW[nb * 8 + (tg ^ sn)];
            bl[nt][1] = sLW[nb * 8 + ((tg + 4) ^ sn)];
        }

        // ---- 3-pass MMA ----
        #pragma unroll
        for (int mt = 0; mt < MT; mt++)
            #pragma unroll
            for (int nt = 0; nt < NTT; nt++) {
                mma_bf16(acc[mt][nt], ah[mt], bh[nt]);
                mma_bf16(acc[mt][nt], ah[mt], bl[nt]);
                mma_bf16(acc[mt][nt], al[mt], bh[nt]);
            }
        __syncthreads();
    }

    // ---- epilogue ----
    #pragma unroll
    for (int mt = 0; mt < MT; mt++) {
        int r0 = bm + wm * TM + mt * 16 + g;
        #pragma unroll
        for (int nt = 0; nt < NTT; nt++) {
            int col = bn + wn * TN + nt * 8 + tg * 2;
            float bi0 = bias[col], bi1 = bias[col + 1];
            float v0 = acc[mt][nt][0] + bi0;
            float v1 = acc[mt][nt][1] + bi1;
            float v2 = acc[mt][nt][2] + bi0;
            float v3 = acc[mt][nt][3] + bi1;
            if (do_relu) {
                v0 = fmaxf(v0, 0.f); v1 = fmaxf(v1, 0.f);
                v2 = fmaxf(v2, 0.f); v3 = fmaxf(v3, 0.f);
            }
            C[(size_t)r0 * ldc + col]           = v0;
            C[(size_t)r0 * ldc + col + 1]       = v1;
            C[(size_t)(r0 + 8) * ldc + col]     = v2;
            C[(size_t)(r0 + 8) * ldc + col + 1] = v3;
        }
    }
}

// ---------------------------------------------------------------------------
// Fused embedding-gather + interaction, v3: interaction on tensor cores.
// One 256-thread block per batch row.
//   phase 1: gather 26 bag-sums (+x row) into smem as bf16 hi/lo pairs,
//            two tasks per thread processed concurrently (MLP=2).
//   phase 2: Z = T @ T^T via 32x32x64 mma (hh+hl+lh), scatter lower triangle.
// ---------------------------------------------------------------------------
__global__ __launch_bounds__(256)
void gather_interact(const int* __restrict__ lS_o,
                     const int* __restrict__ lS_i,
                     const float* __restrict__ emb)
{
    __shared__ uint32_t sH[32 * SROW];   // rows 27..31 = padding (outputs discarded)
    __shared__ uint32_t sL[32 * SROW];
    __shared__ int s_beg[NTAB];
    __shared__ int s_end[NTAB];

    const int b    = blockIdx.x;
    const int tid  = threadIdx.x;
    const int lane = tid & 31;
    const int wid  = tid >> 5;

    if (tid < NTAB) {
        s_beg[tid] = lS_o[tid * BATCH + b];
        s_end[tid] = (b + 1 < BATCH) ? lS_o[tid * BATCH + b + 1] : BATCH;
    }
    // row 0 = x from bottom MLP
    if (tid < 16) {
        float4 v = reinterpret_cast<const float4*>(g_x3 + (size_t)b * EMBD)[tid];
        float hx = bf16_round(v.x), hy = bf16_round(v.y);
        float hz = bf16_round(v.z), hw = bf16_round(v.w);
        int base = tid * 2;
        sH[base]     = pack_bf16x2(hx, hy);
        sL[base]     = pack_bf16x2(v.x - hx, v.y - hy);
        sH[base + 1] = pack_bf16x2(hz, hw);
        sL[base + 1] = pack_bf16x2(v.z - hz, v.w - hw);
    }
    __syncthreads();

    // ---- gather: 416 (table, quad) tasks; thread handles task tid and tid+256
    {
        const int t0 = tid >> 4;
        const int q  = tid & 15;
        const int t1 = t0 + 16;
        const bool has1 = (t1 < NTAB);

        const float* tab0 = emb + (size_t)t0 * VOCAB * EMBD + q * 4;
        const float* tab1 = emb + (size_t)t1 * VOCAB * EMBD + q * 4;

        float4 a0 = make_float4(0.f, 0.f, 0.f, 0.f);
        float4 a1 = make_float4(0.f, 0.f, 0.f, 0.f);

        int p0 = s_beg[t0], e0 = s_end[t0];
        int p1 = has1 ? s_beg[t1] : 0;
        int e1 = has1 ? s_end[t1] : 0;

        while (p0 < e0 || p1 < e1) {
            int i0 = (p0 < e0) ? __ldg(lS_i + t0 * BATCH + p0) : -1;
            int i1 = (p1 < e1) ? __ldg(lS_i + t1 * BATCH + p1) : -1;
            if (i0 >= 0) {
                float4 v = *reinterpret_cast<const float4*>(tab0 + (size_t)i0 * EMBD);
                a0.x += v.x; a0.y += v.y; a0.z += v.z; a0.w += v.w;
                p0++;
            }
            if (i1 >= 0) {
                float4 v = *reinterpret_cast<const float4*>(tab1 + (size_t)i1 * EMBD);
                a1.x += v.x; a1.y += v.y; a1.z += v.z; a1.w += v.w;
                p1++;
            }
        }

        {
            float hx = bf16_round(a0.x), hy = bf16_round(a0.y);
            float hz = bf16_round(a0.z), hw = bf16_round(a0.w);
            int base = (t0 + 1) * SROW + q * 2;
            sH[base]     = pack_bf16x2(hx, hy);
            sL[base]     = pack_bf16x2(a0.x - hx, a0.y - hy);
            sH[base + 1] = pack_bf16x2(hz, hw);
            sL[base + 1] = pack_bf16x2(a0.z - hz, a0.w - hw);
        }
        if (has1) {
            float hx = bf16_round(a1.x), hy = bf16_round(a1.y);
            float hz = bf16_round(a1.z), hw = bf16_round(a1.w);
            int base = (t1 + 1) * SROW + q * 2;
            sH[base]     = pack_bf16x2(hx, hy);
            sL[base]     = pack_bf16x2(a1.x - hx, a1.y - hy);
            sH[base + 1] = pack_bf16x2(hz, hw);
            sL[base + 1] = pack_bf16x2(a1.z - hz, a1.w - hw);
        }
    }
    __syncthreads();

    // ---- interaction: Z = T T^T (32x32x64), 8 warps = 2(m) x 4(n) m16n8 tiles
    const int g  = lane >> 2;
    const int tg = lane & 3;
    const int wm = wid & 1;        // 0..1
    const int wn = wid >> 1;       // 0..3

    float acc[4] = {0.f, 0.f, 0.f, 0.f};
    const int r0 = wm * 16 + g;
    const int r1 = r0 + 8;
    const int nb = wn * 8 + g;

    #pragma unroll
    for (int ks = 0; ks < 4; ks++) {
        int kp = ks * 8 + tg;
        uint32_t ah[4], al[4], bh[2], bl[2];
        ah[0] = sH[r0 * SROW + kp];     al[0] = sL[r0 * SROW + kp];
        ah[1] = sH[r1 * SROW + kp];     al[1] = sL[r1 * SROW + kp];
        ah[2] = sH[r0 * SROW + kp + 4]; al[2] = sL[r0 * SROW + kp + 4];
        ah[3] = sH[r1 * SROW + kp + 4]; al[3] = sL[r1 * SROW + kp + 4];
        bh[0] = sH[nb * SROW + kp];     bl[0] = sL[nb * SROW + kp];
        bh[1] = sH[nb * SROW + kp + 4]; bl[1] = sL[nb * SROW + kp + 4];
        mma_bf16(acc, ah, bh);
        mma_bf16(acc, ah, bl);
        mma_bf16(acc, al, bh);
    }

    float* Rb = g_R + (size_t)b * RDIM;
    if (tid < EMBD) Rb[tid] = g_x3[(size_t)b * EMBD + tid];

    {
        int row = wm * 16 + g;
        int col = wn * 8 + tg * 2;
        if (row < NT1) {
            int base = 64 + row * (row - 1) / 2;
            if (col     < row) Rb[base + col]     = acc[0];
            if (col + 1 < row) Rb[base + col + 1] = acc[1];
        }
        int row2 = row + 8;
        if (row2 < NT1) {
            int base = 64 + row2 * (row2 - 1) / 2;
            if (col     < row2) Rb[base + col]     = acc[2];
            if (col + 1 < row2) Rb[base + col + 1] = acc[3];
        }
    }
}

// ---------------------------------------------------------------------------
// Final layer: out[b] = sigmoid( dot(z2[b], tw2) + tb2 ). One warp per row.
// ---------------------------------------------------------------------------
__global__ __launch_bounds__(256)
void top_final(const float* __restrict__ w,
               const float* __restrict__ bias,
               float* __restrict__ out)
{
    int gwarp = (blockIdx.x * blockDim.x + threadIdx.x) >> 5;
    int lane  = threadIdx.x & 31;
    if (gwarp >= BATCH) return;

    const float* z = g_z2 + (size_t)gwarp * 256;
    float s = 0.f;
    #pragma unroll
    for (int k = lane; k < 256; k += 32) s = fmaf(z[k], w[k], s);
    #pragma unroll
    for (int o = 16; o; o >>= 1) s += __shfl_xor_sync(0xFFFFFFFFu, s, o);
    if (lane == 0) out[gwarp] = 1.f / (1.f + expf(-(s + bias[0])));
}

// ---------------------------------------------------------------------------
extern "C" void kernel_launch(void* const* d_in, const int* in_sizes, int n_in,
                              void* d_out, int out_size)
{
    const float* dense_x = (const float*)d_in[0];
    const int*   lS_o    = (const int*)  d_in[1];
    const int*   lS_i    = (const int*)  d_in[2];
    const float* emb     = (const float*)d_in[3];
    const float* bw0     = (const float*)d_in[4];
    const float* bb0     = (const float*)d_in[5];
    const float* bw1     = (const float*)d_in[6];
    const float* bb1     = (const float*)d_in[7];
    const float* bw2     = (const float*)d_in[8];
    const float* bb2     = (const float*)d_in[9];
    const float* tw0     = (const float*)d_in[10];
    const float* tb0     = (const float*)d_in[11];
    const float* tw1     = (const float*)d_in[12];
    const float* tb1     = (const float*)d_in[13];
    const float* tw2     = (const float*)d_in[14];
    const float* tb2     = (const float*)d_in[15];
    float* out = (float*)d_out;

    float *x1, *x2, *x3, *R, *z1, *z2;
    cudaGetSymbolAddress((void**)&x1, g_x1);
    cudaGetSymbolAddress((void**)&x2, g_x2);
    cudaGetSymbolAddress((void**)&x3, g_x3);
    cudaGetSymbolAddress((void**)&R,  g_R);
    cudaGetSymbolAddress((void**)&z1, g_z1);
    cudaGetSymbolAddress((void**)&z2, g_z2);

    // Bottom MLP (tensor cores)
    gemm_nt_mma<128, 64, 4, 2><<<dim3(512 / 64, BATCH / 128), 256>>>(
        dense_x, bw0, bb0, x1, 13, 13, 13, 512, 1);
    gemm_nt_mma<64, 128, 2, 4><<<dim3(256 / 128, BATCH / 64), 256>>>(
        x1, bw1, bb1, x2, 512, 512, 512, 256, 1);
    gemm_nt_mma<64, 64, 4, 2><<<dim3(64 / 64, BATCH / 64), 256>>>(
        x2, bw2, bb2, x3, 256, 256, 256, 64, 1);

    // Fused gather + interaction -> R
    gather_interact<<<BATCH, 256>>>(lS_o, lS_i, emb);

    // Top MLP (tensor cores)
    gemm_nt_mma<128, 128, 2, 4><<<dim3(512 / 128, BATCH / 128), 256>>>(
        R, tw0, tb0, z1, RDIM, RDIM, RDIM, 512, 1);
    gemm_nt_mma<64, 128, 2, 4><<<dim3(256 / 128, BATCH / 64), 256>>>(
        z1, tw1, tb1, z2, 512, 512, 512, 256, 1);
    top_final<<<(BATCH * 32 + 255) / 256, 256>>>(tw2, tb2, out);
}

// round 7
// speedup vs baseline: 2.9856x; 1.1414x over previous
#include <cuda_runtime.h>
#include <cuda_bf16.h>
#include <math.h>
#include <stdint.h>

#define BATCH 4096
#define NDENSE 13
#define NTAB 26
#define VOCAB 100000
#define EMBD 64
#define NT1 27            // tables + 1
#define NPAIR 351         // 27*26/2
#define RDIM 415          // 64 + 351
#define SROW 36           // u32 stride of T row: bank = 4*row + col (mod 32) -> conflict-free frags

// Intermediates (allocation-free scratch)
__device__ float g_x1[BATCH * 512];
__device__ float g_x2[BATCH * 256];
__device__ float g_x3[BATCH * 64];
__device__ float g_R [BATCH * RDIM];
__device__ float g_z1[BATCH * 512];
__device__ float g_z2[BATCH * 256];

__device__ __forceinline__ uint32_t pack_bf16x2(float lo, float hi)
{
    __nv_bfloat162 p = __floats2bfloat162_rn(lo, hi);
    return *reinterpret_cast<uint32_t*>(&p);
}

__device__ __forceinline__ float bf16_round(float v)
{
    return __bfloat162float(__float2bfloat16(v));
}

__device__ __forceinline__ void mma_bf16(float* c, const uint32_t* a, const uint32_t* b)
{
    asm volatile(
        "mma.sync.aligned.m16n8k16.row.col.f32.bf16.bf16.f32 "
        "{%0,%1,%2,%3}, {%4,%5,%6,%7}, {%8,%9}, {%0,%1,%2,%3};"
        : "+f"(c[0]), "+f"(c[1]), "+f"(c[2]), "+f"(c[3])
        : "r"(a[0]), "r"(a[1]), "r"(a[2]), "r"(a[3]), "r"(b[0]), "r"(b[1]));
}

// ---------------------------------------------------------------------------
// Templated NT GEMM on tensor cores: C = act(A @ W^T + bias).
// bf16 hi/lo split, 3-pass (hh+hl+lh) fp32 accumulation (~1e-7 accuracy).
// 256 threads = 8 warps arranged WM_ x WN_; warp tile (BM/WM_) x (BN/WN_).
// Register-prefetch pipeline on the K loop (BK = 16 fp32).
// ---------------------------------------------------------------------------
template<int BM, int BN, int WM_, int WN_>
__global__ __launch_bounds__(256)
void gemm_nt_mma(const float* __restrict__ A,
                 const float* __restrict__ W,
                 const float* __restrict__ bias,
                 float* __restrict__ C,
                 int K, int lda, int ldw, int ldc, int do_relu)
{
    constexpr int TM  = BM / WM_;
    constexpr int TN  = BN / WN_;
    constexpr int MT  = TM / 16;
    constexpr int NTT = TN / 8;
    constexpr int AR  = BM / 32;
    constexpr int WR  = BN / 32;

    __shared__ uint32_t sHA[BM * 8];
    __shared__ uint32_t sLA[BM * 8];
    __shared__ uint32_t sHW[BN * 8];
    __shared__ uint32_t sLW[BN * 8];

    const int tid  = threadIdx.x;
    const int lane = tid & 31;
    const int wid  = tid >> 5;
    const int wm   = wid % WM_;
    const int wn   = wid / WM_;
    const int g    = lane >> 2;
    const int tg   = lane & 3;
    const int bm   = blockIdx.y * BM;
    const int bn   = blockIdx.x * BN;

    const int pr   = tid & 7;
    const int row0 = tid >> 3;

    float acc[MT][NTT][4];
    #pragma unroll
    for (int i = 0; i < MT; i++)
        #pragma unroll
        for (int j = 0; j < NTT; j++)
            #pragma unroll
            for (int q = 0; q < 4; q++) acc[i][j][q] = 0.f;

    float pa[AR][2], pw[WR][2];

    {
        int kk = pr * 2;
        #pragma unroll
        for (int r = 0; r < AR; r++) {
            const float* ap = A + (size_t)(bm + row0 + r * 32) * lda;
            pa[r][0] = (kk     < K) ? __ldg(ap + kk)     : 0.f;
            pa[r][1] = (kk + 1 < K) ? __ldg(ap + kk + 1) : 0.f;
        }
        #pragma unroll
        for (int r = 0; r < WR; r++) {
            const float* wp = W + (size_t)(bn + row0 + r * 32) * ldw;
            pw[r][0] = (kk     < K) ? __ldg(wp + kk)     : 0.f;
            pw[r][1] = (kk + 1 < K) ? __ldg(wp + kk + 1) : 0.f;
        }
    }

    for (int k0 = 0; k0 < K; k0 += 16) {
        #pragma unroll
        for (int r = 0; r < AR; r++) {
            int m = row0 + r * 32;
            float h0 = bf16_round(pa[r][0]);
            float h1 = bf16_round(pa[r][1]);
            int idx = m * 8 + (pr ^ (m & 7));
            sHA[idx] = pack_bf16x2(h0, h1);
            sLA[idx] = pack_bf16x2(pa[r][0] - h0, pa[r][1] - h1);
        }
        #pragma unroll
        for (int r = 0; r < WR; r++) {
            int n = row0 + r * 32;
            float h0 = bf16_round(pw[r][0]);
            float h1 = bf16_round(pw[r][1]);
            int idx = n * 8 + (pr ^ (n & 7));
            sHW[idx] = pack_bf16x2(h0, h1);
            sLW[idx] = pack_bf16x2(pw[r][0] - h0, pw[r][1] - h1);
        }
        __syncthreads();

        if (k0 + 16 < K) {
            int kk = k0 + 16 + pr * 2;
            #pragma unroll
            for (int r = 0; r < AR; r++) {
                const float* ap = A + (size_t)(bm + row0 + r * 32) * lda;
                pa[r][0] = (kk     < K) ? __ldg(ap + kk)     : 0.f;
                pa[r][1] = (kk + 1 < K) ? __ldg(ap + kk + 1) : 0.f;
            }
            #pragma unroll
            for (int r = 0; r < WR; r++) {
                const float* wp = W + (size_t)(bn + row0 + r * 32) * ldw;
                pw[r][0] = (kk     < K) ? __ldg(wp + kk)     : 0.f;
                pw[r][1] = (kk + 1 < K) ? __ldg(wp + kk + 1) : 0.f;
            }
        }

        uint32_t ah[MT][4], al[MT][4], bh[NTT][2], bl[NTT][2];
        #pragma unroll
        for (int mt = 0; mt < MT; mt++) {
            int r0 = wm * TM + mt * 16 + g;
            int r1 = r0 + 8;
            int s0 = r0 & 7, s1 = r1 & 7;
            ah[mt][0] = sHA[r0 * 8 + (tg ^ s0)];
            ah[mt][1] = sHA[r1 * 8 + (tg ^ s1)];
            ah[mt][2] = sHA[r0 * 8 + ((tg + 4) ^ s0)];
            ah[mt][3] = sHA[r1 * 8 + ((tg + 4) ^ s1)];
            al[mt][0] = sLA[r0 * 8 + (tg ^ s0)];
            al[mt][1] = sLA[r1 * 8 + (tg ^ s1)];
            al[mt][2] = sLA[r0 * 8 + ((tg + 4) ^ s0)];
            al[mt][3] = sLA[r1 * 8 + ((tg + 4) ^ s1)];
        }
        #pragma unroll
        for (int nt = 0; nt < NTT; nt++) {
            int nb = wn * TN + nt * 8 + g;
            int sn = nb & 7;
            bh[nt][0] = sHW[nb * 8 + (tg ^ sn)];
            bh[nt][1] = sHW[nb * 8 + ((tg + 4) ^ sn)];
            bl[nt][0] = sLW[nb * 8 + (tg ^ sn)];
            bl[nt][1] = sLW[nb * 8 + ((tg + 4) ^ sn)];
        }

        #pragma unroll
        for (int mt = 0; mt < MT; mt++)
            #pragma unroll
            for (int nt = 0; nt < NTT; nt++) {
                mma_bf16(acc[mt][nt], ah[mt], bh[nt]);
                mma_bf16(acc[mt][nt], ah[mt], bl[nt]);
                mma_bf16(acc[mt][nt], al[mt], bh[nt]);
            }
        __syncthreads();
    }

    #pragma unroll
    for (int mt = 0; mt < MT; mt++) {
        int r0 = bm + wm * TM + mt * 16 + g;
        #pragma unroll
        for (int nt = 0; nt < NTT; nt++) {
            int col = bn + wn * TN + nt * 8 + tg * 2;
            float bi0 = bias[col], bi1 = bias[col + 1];
            float v0 = acc[mt][nt][0] + bi0;
            float v1 = acc[mt][nt][1] + bi1;
            float v2 = acc[mt][nt][2] + bi0;
            float v3 = acc[mt][nt][3] + bi1;
            if (do_relu) {
                v0 = fmaxf(v0, 0.f); v1 = fmaxf(v1, 0.f);
                v2 = fmaxf(v2, 0.f); v3 = fmaxf(v3, 0.f);
            }
            C[(size_t)r0 * ldc + col]           = v0;
            C[(size_t)r0 * ldc + col + 1]       = v1;
            C[(size_t)(r0 + 8) * ldc + col]     = v2;
            C[(size_t)(r0 + 8) * ldc + col + 1] = v3;
        }
    }
}

// ---------------------------------------------------------------------------
// Fused embedding-gather + interaction, v4.
//  - indices prefetched to smem (len==1 fast path) -> gather = 1 global load
//  - SROW=36 -> conflict-free MMA fragment LDS
//  - Z staged in smem -> coalesced R stores
// ---------------------------------------------------------------------------
__global__ __launch_bounds__(256)
void gather_interact(const int* __restrict__ lS_o,
                     const int* __restrict__ lS_i,
                     const float* __restrict__ emb)
{
    __shared__ uint32_t sH[32 * SROW];   // rows 27..31 padding (outputs discarded)
    __shared__ uint32_t sL[32 * SROW];
    __shared__ float    sZ[NPAIR];
    __shared__ int s_beg[NTAB];
    __shared__ int s_len[NTAB];
    __shared__ int s_idx[NTAB];

    const int b    = blockIdx.x;
    const int tid  = threadIdx.x;
    const int lane = tid & 31;
    const int wid  = tid >> 5;

    if (tid < NTAB) {
        int beg = lS_o[tid * BATCH + b];
        int end = (b + 1 < BATCH) ? lS_o[tid * BATCH + b + 1] : BATCH;
        s_beg[tid] = beg;
        s_len[tid] = end - beg;
        s_idx[tid] = (end - beg == 1) ? __ldg(lS_i + tid * BATCH + beg) : -1;
    }
    // row 0 = x from bottom MLP
    if (tid < 16) {
        float4 v = reinterpret_cast<const float4*>(g_x3 + (size_t)b * EMBD)[tid];
        float hx = bf16_round(v.x), hy = bf16_round(v.y);
        float hz = bf16_round(v.z), hw = bf16_round(v.w);
        int base = tid * 2;
        sH[base]     = pack_bf16x2(hx, hy);
        sL[base]     = pack_bf16x2(v.x - hx, v.y - hy);
        sH[base + 1] = pack_bf16x2(hz, hw);
        sL[base + 1] = pack_bf16x2(v.z - hz, v.w - hw);
    }
    __syncthreads();

    // ---- gather: 416 (table, quad) tasks; thread handles tasks tid, tid+256
    {
        const int t0 = tid >> 4;
        const int q  = tid & 15;
        const int t1 = t0 + 16;
        const bool has1 = (t1 < NTAB);

        const float* tab0 = emb + (size_t)t0 * VOCAB * EMBD + q * 4;
        const float* tab1 = emb + (size_t)t1 * VOCAB * EMBD + q * 4;

        float4 a0 = make_float4(0.f, 0.f, 0.f, 0.f);
        float4 a1 = make_float4(0.f, 0.f, 0.f, 0.f);

        int i0f = s_idx[t0];
        int i1f = has1 ? s_idx[t1] : 0;

        if (i0f >= 0 && i1f >= 0) {
            // fast path: both bags length 1, indices already in smem.
            // two independent loads -> MLP=2, chain depth 1.
            if (has1) {
                float4 v0 = *reinterpret_cast<const float4*>(tab0 + (size_t)i0f * EMBD);
                float4 v1 = *reinterpret_cast<const float4*>(tab1 + (size_t)i1f * EMBD);
                a0 = v0; a1 = v1;
            } else {
                a0 = *reinterpret_cast<const float4*>(tab0 + (size_t)i0f * EMBD);
            }
        } else {
            // general path
            int p0 = s_beg[t0], e0 = p0 + s_len[t0];
            int p1 = has1 ? s_beg[t1] : 0;
            int e1 = has1 ? (p1 + s_len[t1]) : 0;
            while (p0 < e0 || p1 < e1) {
                int i0 = (p0 < e0) ? __ldg(lS_i + t0 * BATCH + p0) : -1;
                int i1 = (p1 < e1) ? __ldg(lS_i + t1 * BATCH + p1) : -1;
                if (i0 >= 0) {
                    float4 v = *reinterpret_cast<const float4*>(tab0 + (size_t)i0 * EMBD);
                    a0.x += v.x; a0.y += v.y; a0.z += v.z; a0.w += v.w;
                    p0++;
                }
                if (i1 >= 0) {
                    float4 v = *reinterpret_cast<const float4*>(tab1 + (size_t)i1 * EMBD);
                    a1.x += v.x; a1.y += v.y; a1.z += v.z; a1.w += v.w;
                    p1++;
                }
            }
        }

        {
            float hx = bf16_round(a0.x), hy = bf16_round(a0.y);
            float hz = bf16_round(a0.z), hw = bf16_round(a0.w);
            int base = (t0 + 1) * SROW + q * 2;
            sH[base]     = pack_bf16x2(hx, hy);
            sL[base]     = pack_bf16x2(a0.x - hx, a0.y - hy);
            sH[base + 1] = pack_bf16x2(hz, hw);
            sL[base + 1] = pack_bf16x2(a0.z - hz, a0.w - hw);
        }
        if (has1) {
            float hx = bf16_round(a1.x), hy = bf16_round(a1.y);
            float hz = bf16_round(a1.z), hw = bf16_round(a1.w);
            int base = (t1 + 1) * SROW + q * 2;
            sH[base]     = pack_bf16x2(hx, hy);
            sL[base]     = pack_bf16x2(a1.x - hx, a1.y - hy);
            sH[base + 1] = pack_bf16x2(hz, hw);
            sL[base + 1] = pack_bf16x2(a1.z - hz, a1.w - hw);
        }
    }
    __syncthreads();

    // ---- interaction: Z = T T^T (32x32x64), 8 warps = 2(m) x 4(n) m16n8 tiles
    const int g  = lane >> 2;
    const int tg = lane & 3;
    const int wm = wid & 1;
    const int wn = wid >> 1;

    float acc[4] = {0.f, 0.f, 0.f, 0.f};
    const int r0 = wm * 16 + g;
    const int r1 = r0 + 8;
    const int nb = wn * 8 + g;

    #pragma unroll
    for (int ks = 0; ks < 4; ks++) {
        int kp = ks * 8 + tg;
        uint32_t ah[4], al[4], bh[2], bl[2];
        ah[0] = sH[r0 * SROW + kp];     al[0] = sL[r0 * SROW + kp];
        ah[1] = sH[r1 * SROW + kp];     al[1] = sL[r1 * SROW + kp];
        ah[2] = sH[r0 * SROW + kp + 4]; al[2] = sL[r0 * SROW + kp + 4];
        ah[3] = sH[r1 * SROW + kp + 4]; al[3] = sL[r1 * SROW + kp + 4];
        bh[0] = sH[nb * SROW + kp];     bl[0] = sL[nb * SROW + kp];
        bh[1] = sH[nb * SROW + kp + 4]; bl[1] = sL[nb * SROW + kp + 4];
        mma_bf16(acc, ah, bh);
        mma_bf16(acc, ah, bl);
        mma_bf16(acc, al, bh);
    }

    // stage lower triangle into smem
    {
        int row = wm * 16 + g;
        int col = wn * 8 + tg * 2;
        if (row < NT1) {
            int base = row * (row - 1) / 2;
            if (col     < row) sZ[base + col]     = acc[0];
            if (col + 1 < row) sZ[base + col + 1] = acc[1];
        }
        int row2 = row + 8;
        if (row2 < NT1) {
            int base = row2 * (row2 - 1) / 2;
            if (col     < row2) sZ[base + col]     = acc[2];
            if (col + 1 < row2) sZ[base + col + 1] = acc[3];
        }
    }
    __syncthreads();

    // coalesced R writes
    float* Rb = g_R + (size_t)b * RDIM;
    if (tid < EMBD) Rb[tid] = g_x3[(size_t)b * EMBD + tid];
    for (int p = tid; p < NPAIR; p += 256) Rb[64 + p] = sZ[p];
}

// ---------------------------------------------------------------------------
// Final layer: out[b] = sigmoid( dot(z2[b], tw2) + tb2 ). One warp per row.
// ---------------------------------------------------------------------------
__global__ __launch_bounds__(256)
void top_final(const float* __restrict__ w,
               const float* __restrict__ bias,
               float* __restrict__ out)
{
    int gwarp = (blockIdx.x * blockDim.x + threadIdx.x) >> 5;
    int lane  = threadIdx.x & 31;
    if (gwarp >= BATCH) return;

    const float* z = g_z2 + (size_t)gwarp * 256;
    float s = 0.f;
    #pragma unroll
    for (int k = lane; k < 256; k += 32) s = fmaf(z[k], w[k], s);
    #pragma unroll
    for (int o = 16; o; o >>= 1) s += __shfl_xor_sync(0xFFFFFFFFu, s, o);
    if (lane == 0) out[gwarp] = 1.f / (1.f + expf(-(s + bias[0])));
}

// ---------------------------------------------------------------------------
extern "C" void kernel_launch(void* const* d_in, const int* in_sizes, int n_in,
                              void* d_out, int out_size)
{
    const float* dense_x = (const float*)d_in[0];
    const int*   lS_o    = (const int*)  d_in[1];
    const int*   lS_i    = (const int*)  d_in[2];
    const float* emb     = (const float*)d_in[3];
    const float* bw0     = (const float*)d_in[4];
    const float* bb0     = (const float*)d_in[5];
    const float* bw1     = (const float*)d_in[6];
    const float* bb1     = (const float*)d_in[7];
    const float* bw2     = (const float*)d_in[8];
    const float* bb2     = (const float*)d_in[9];
    const float* tw0     = (const float*)d_in[10];
    const float* tb0     = (const float*)d_in[11];
    const float* tw1     = (const float*)d_in[12];
    const float* tb1     = (const float*)d_in[13];
    const float* tw2     = (const float*)d_in[14];
    const float* tb2     = (const float*)d_in[15];
    float* out = (float*)d_out;

    float *x1, *x2, *x3, *R, *z1, *z2;
    cudaGetSymbolAddress((void**)&x1, g_x1);
    cudaGetSymbolAddress((void**)&x2, g_x2);
    cudaGetSymbolAddress((void**)&x3, g_x3);
    cudaGetSymbolAddress((void**)&R,  g_R);
    cudaGetSymbolAddress((void**)&z1, g_z1);
    cudaGetSymbolAddress((void**)&z2, g_z2);

    // Bottom MLP (tensor cores)
    gemm_nt_mma<128, 64, 4, 2><<<dim3(512 / 64, BATCH / 128), 256>>>(
        dense_x, bw0, bb0, x1, 13, 13, 13, 512, 1);
    gemm_nt_mma<64, 128, 2, 4><<<dim3(256 / 128, BATCH / 64), 256>>>(
        x1, bw1, bb1, x2, 512, 512, 512, 256, 1);
    gemm_nt_mma<64, 64, 4, 2><<<dim3(64 / 64, BATCH / 64), 256>>>(
        x2, bw2, bb2, x3, 256, 256, 256, 64, 1);

    // Fused gather + interaction -> R
    gather_interact<<<BATCH, 256>>>(lS_o, lS_i, emb);

    // Top MLP (tensor cores)
    gemm_nt_mma<128, 128, 2, 4><<<dim3(512 / 128, BATCH / 128), 256>>>(
        R, tw0, tb0, z1, RDIM, RDIM, RDIM, 512, 1);
    gemm_nt_mma<64, 128, 2, 4><<<dim3(256 / 128, BATCH / 64), 256>>>(
        z1, tw1, tb1, z2, 512, 512, 512, 256, 1);
    top_final<<<(BATCH * 32 + 255) / 256, 256>>>(tw2, tb2, out);
}

// round 9
// speedup vs baseline: 3.2820x; 1.0993x over previous
#include <cuda_runtime.h>
#include <cuda_bf16.h>
#include <math.h>
#include <stdint.h>

#define BATCH 4096
#define NTAB 26
#define VOCAB 100000
#define EMBD 64
#define NT1 27
#define NPAIR 351
#define RDIM 415
#define RP 208            // pairs per R row
#define SROW 36           // interact smem row stride (u32)
#define SROWG 20          // gemm smem row stride (u32): 16 data pairs + 4 pad

// ---- pre-split weight / input buffers (hi/lo bf16x2 pairs) ----
__device__ uint32_t g_dxh[BATCH * 7],  g_dxl[BATCH * 7];
__device__ uint32_t g_w0h[512 * 7],    g_w0l[512 * 7];
__device__ uint32_t g_w1h[256 * 256],  g_w1l[256 * 256];
__device__ uint32_t g_w2h[64 * 128],   g_w2l[64 * 128];
__device__ uint32_t g_t0h[512 * 208],  g_t0l[512 * 208];
__device__ uint32_t g_t1h[256 * 256],  g_t1l[256 * 256];
// ---- split activations ----
__device__ uint32_t g_x1h[BATCH * 256], g_x1l[BATCH * 256];
__device__ uint32_t g_x2h[BATCH * 128], g_x2l[BATCH * 128];
__device__ uint32_t g_x3h[BATCH * 32],  g_x3l[BATCH * 32];
__device__ uint32_t g_Rh [BATCH * RP],  g_Rl [BATCH * RP];
__device__ uint32_t g_z1h[BATCH * 256], g_z1l[BATCH * 256];
__device__ float    g_z2 [BATCH * 256];

__device__ __forceinline__ uint32_t pack_bf16x2(float lo, float hi)
{
    __nv_bfloat162 p = __floats2bfloat162_rn(lo, hi);
    return *reinterpret_cast<uint32_t*>(&p);
}
__device__ __forceinline__ float bf16_round(float v)
{
    return __bfloat162float(__float2bfloat16(v));
}
__device__ __forceinline__ void mma_bf16(float* c, const uint32_t* a, const uint32_t* b)
{
    asm volatile(
        "mma.sync.aligned.m16n8k16.row.col.f32.bf16.bf16.f32 "
        "{%0,%1,%2,%3}, {%4,%5,%6,%7}, {%8,%9}, {%0,%1,%2,%3};"
        : "+f"(c[0]), "+f"(c[1]), "+f"(c[2]), "+f"(c[3])
        : "r"(a[0]), "r"(a[1]), "r"(a[2]), "r"(a[3]), "r"(b[0]), "r"(b[1]));
}
__device__ __forceinline__ void ldm_x4(uint32_t* r, const uint32_t* p)
{
    uint32_t a = (uint32_t)__cvta_generic_to_shared(p);
    asm volatile("ldmatrix.sync.aligned.m8n8.x4.shared.b16 {%0,%1,%2,%3}, [%4];"
        : "=r"(r[0]), "=r"(r[1]), "=r"(r[2]), "=r"(r[3]) : "r"(a));
}

// ---------------------------------------------------------------------------
// Split dense_x + 5 weight matrices into bf16 hi/lo pair arrays.
// Item space: (matrix, row, pair) flattened; 278016 items total.
// ---------------------------------------------------------------------------
__global__ __launch_bounds__(256)
void split_all(const float* __restrict__ dx, const float* __restrict__ w0,
               const float* __restrict__ w1, const float* __restrict__ w2,
               const float* __restrict__ t0, const float* __restrict__ t1)
{
    int i = blockIdx.x * 256 + threadIdx.x;
    if (i >= 278016) return;
    const float* src; uint32_t *dh, *dl; int K, P, local;
    if (i < 28672)       { src = dx; dh = g_dxh; dl = g_dxl; K = 13;  P = 7;   local = i; }
    else if (i < 32256)  { src = w0; dh = g_w0h; dl = g_w0l; K = 13;  P = 7;   local = i - 28672; }
    else if (i < 97792)  { src = w1; dh = g_w1h; dl = g_w1l; K = 512; P = 256; local = i - 32256; }
    else if (i < 105984) { src = w2; dh = g_w2h; dl = g_w2l; K = 256; P = 128; local = i - 97792; }
    else if (i < 212480) { src = t0; dh = g_t0h; dl = g_t0l; K = 415; P = 208; local = i - 105984; }
    else                 { src = t1; dh = g_t1h; dl = g_t1l; K = 512; P = 256; local = i - 212480; }
    int row = local / P, p = local - row * P, k = 2 * p;
    float v0 = src[(size_t)row * K + k];
    float v1 = (k + 1 < K) ? src[(size_t)row * K + k + 1] : 0.f;
    float h0 = bf16_round(v0), h1 = bf16_round(v1);
    dh[local] = pack_bf16x2(h0, h1);
    dl[local] = pack_bf16x2(v0 - h0, v1 - h1);
}

// ---------------------------------------------------------------------------
// NT GEMM on tensor cores, pre-split inputs: C = relu(A @ W^T + bias).
// A/W given as bf16x2 hi/lo pair arrays (k-pairs). 3-pass hh+hl+lh, fp32 acc.
// BK=32 (16 pairs/stage), ldmatrix.x4 fragment loads, stride-20 padded smem.
// Output either split pairs (Ch/Cl, ldc=pairs) or fp32 (Cf, ldc=elems).
// ---------------------------------------------------------------------------
template<int BM, int BN, int WM_, int WN_, bool SPLIT_OUT>
__global__ __launch_bounds__(256)
void gemm_nt_mma(const uint32_t* __restrict__ Ah, const uint32_t* __restrict__ Al,
                 const uint32_t* __restrict__ Wh, const uint32_t* __restrict__ Wl,
                 const float* __restrict__ bias,
                 uint32_t* __restrict__ Ch, uint32_t* __restrict__ Cl,
                 float* __restrict__ Cf,
                 int Kp, int ldap, int ldwp, int ldc)
{
    constexpr int TM  = BM / WM_;
    constexpr int TN  = BN / WN_;
    constexpr int MT  = TM / 16;
    constexpr int NTT = TN / 8;
    constexpr int NT2 = NTT / 2;
    constexpr int ARW = BM / 16;   // A rows per thread (stride 16)
    constexpr int WRW = BN / 16;

    __shared__ __align__(16) uint32_t sHA[BM * SROWG];
    __shared__ __align__(16) uint32_t sLA[BM * SROWG];
    __shared__ __align__(16) uint32_t sHW[BN * SROWG];
    __shared__ __align__(16) uint32_t sLW[BN * SROWG];

    const int tid  = threadIdx.x;
    const int lane = tid & 31;
    const int wid  = tid >> 5;
    const int wm   = wid % WM_;
    const int wn   = wid / WM_;
    const int g    = lane >> 2;
    const int tg   = lane & 3;
    const int bm   = blockIdx.y * BM;
    const int bn   = blockIdx.x * BN;

    const int pp   = tid & 15;     // pair slot 0..15 within stage
    const int row0 = tid >> 4;     // 0..15

    const int sub_r  = lane & 7;
    const int quad   = lane >> 3;
    const int lm_row = sub_r + (quad & 1) * 8;
    const int lm_col = (quad >> 1) * 4;

    float acc[MT][NTT][4];
    #pragma unroll
    for (int i = 0; i < MT; i++)
        #pragma unroll
        for (int j = 0; j < NTT; j++)
            #pragma unroll
            for (int q = 0; q < 4; q++) acc[i][j][q] = 0.f;

    uint32_t pah[ARW], pal[ARW], pwh[WRW], pwl[WRW];

    // prefetch stage 0
    {
        int pi = pp;
        bool ok = pi < Kp;
        #pragma unroll
        for (int r = 0; r < ARW; r++) {
            size_t off = (size_t)(bm + row0 + r * 16) * ldap + pi;
            pah[r] = ok ? __ldg(Ah + off) : 0u;
            pal[r] = ok ? __ldg(Al + off) : 0u;
        }
        #pragma unroll
        for (int r = 0; r < WRW; r++) {
            size_t off = (size_t)(bn + row0 + r * 16) * ldwp + pi;
            pwh[r] = ok ? __ldg(Wh + off) : 0u;
            pwl[r] = ok ? __ldg(Wl + off) : 0u;
        }
    }

    const int ntiles = (Kp + 15) / 16;
    for (int t = 0; t < ntiles; t++) {
        #pragma unroll
        for (int r = 0; r < ARW; r++) {
            int idx = (row0 + r * 16) * SROWG + pp;
            sHA[idx] = pah[r];
            sLA[idx] = pal[r];
        }
        #pragma unroll
        for (int r = 0; r < WRW; r++) {
            int idx = (row0 + r * 16) * SROWG + pp;
            sHW[idx] = pwh[r];
            sLW[idx] = pwl[r];
        }
        __syncthreads();

        if (t + 1 < ntiles) {
            int pi = (t + 1) * 16 + pp;
            bool ok = pi < Kp;
            #pragma unroll
            for (int r = 0; r < ARW; r++) {
                size_t off = (size_t)(bm + row0 + r * 16) * ldap + pi;
                pah[r] = ok ? __ldg(Ah + off) : 0u;
                pal[r] = ok ? __ldg(Al + off) : 0u;
            }
            #pragma unroll
            for (int r = 0; r < WRW; r++) {
                size_t off = (size_t)(bn + row0 + r * 16) * ldwp + pi;
                pwh[r] = ok ? __ldg(Wh + off) : 0u;
                pwl[r] = ok ? __ldg(Wl + off) : 0u;
            }
        }

        #pragma unroll
        for (int ks = 0; ks < 2; ks++) {
            const int cb = ks * 8;
            uint32_t ah[MT][4], al[MT][4], bh[NTT][2], bl[NTT][2];
            #pragma unroll
            for (int mt = 0; mt < MT; mt++) {
                int base = (wm * TM + mt * 16 + lm_row) * SROWG + cb + lm_col;
                ldm_x4(ah[mt], &sHA[base]);
                ldm_x4(al[mt], &sLA[base]);
            }
            #pragma unroll
            for (int n2 = 0; n2 < NT2; n2++) {
                int base = (wn * TN + n2 * 16 + lm_row) * SROWG + cb + lm_col;
                uint32_t q[4];
                ldm_x4(q, &sHW[base]);
                bh[2 * n2][0] = q[0]; bh[2 * n2 + 1][0] = q[1];
                bh[2 * n2][1] = q[2]; bh[2 * n2 + 1][1] = q[3];
                ldm_x4(q, &sLW[base]);
                bl[2 * n2][0] = q[0]; bl[2 * n2 + 1][0] = q[1];
                bl[2 * n2][1] = q[2]; bl[2 * n2 + 1][1] = q[3];
            }
            #pragma unroll
            for (int mt = 0; mt < MT; mt++)
                #pragma unroll
                for (int nt = 0; nt < NTT; nt++) {
                    mma_bf16(acc[mt][nt], ah[mt], bh[nt]);
                    mma_bf16(acc[mt][nt], ah[mt], bl[nt]);
                    mma_bf16(acc[mt][nt], al[mt], bh[nt]);
                }
        }
        __syncthreads();
    }

    // epilogue
    #pragma unroll
    for (int mt = 0; mt < MT; mt++) {
        int r0 = bm + wm * TM + mt * 16 + g;
        #pragma unroll
        for (int nt = 0; nt < NTT; nt++) {
            int col = bn + wn * TN + nt * 8 + tg * 2;
            float bi0 = bias[col], bi1 = bias[col + 1];
            float v0 = fmaxf(acc[mt][nt][0] + bi0, 0.f);
            float v1 = fmaxf(acc[mt][nt][1] + bi1, 0.f);
            float v2 = fmaxf(acc[mt][nt][2] + bi0, 0.f);
            float v3 = fmaxf(acc[mt][nt][3] + bi1, 0.f);
            if (SPLIT_OUT) {
                int pj = col >> 1;
                float h0 = bf16_round(v0), h1 = bf16_round(v1);
                Ch[(size_t)r0 * ldc + pj] = pack_bf16x2(h0, h1);
                Cl[(size_t)r0 * ldc + pj] = pack_bf16x2(v0 - h0, v1 - h1);
                float h2 = bf16_round(v2), h3 = bf16_round(v3);
                Ch[(size_t)(r0 + 8) * ldc + pj] = pack_bf16x2(h2, h3);
                Cl[(size_t)(r0 + 8) * ldc + pj] = pack_bf16x2(v2 - h2, v3 - h3);
            } else {
                Cf[(size_t)r0 * ldc + col]           = v0;
                Cf[(size_t)r0 * ldc + col + 1]       = v1;
                Cf[(size_t)(r0 + 8) * ldc + col]     = v2;
                Cf[(size_t)(r0 + 8) * ldc + col + 1] = v3;
            }
        }
    }
}

// ---------------------------------------------------------------------------
// Fused embedding-gather + interaction, v5 (split-pair I/O).
// ---------------------------------------------------------------------------
__global__ __launch_bounds__(256)
void gather_interact(const int* __restrict__ lS_o,
                     const int* __restrict__ lS_i,
                     const float* __restrict__ emb)
{
    __shared__ uint32_t sH[32 * SROW];
    __shared__ uint32_t sL[32 * SROW];
    __shared__ float    sZ[NPAIR];
    __shared__ int s_beg[NTAB];
    __shared__ int s_len[NTAB];
    __shared__ int s_idx[NTAB];

    const int b    = blockIdx.x;
    const int tid  = threadIdx.x;
    const int lane = tid & 31;
    const int wid  = tid >> 5;

    if (tid < NTAB) {
        int beg = lS_o[tid * BATCH + b];
        int end = (b + 1 < BATCH) ? lS_o[tid * BATCH + b + 1] : BATCH;
        s_beg[tid] = beg;
        s_len[tid] = end - beg;
        s_idx[tid] = (end - beg == 1) ? __ldg(lS_i + tid * BATCH + beg) : -1;
    }
    // row 0 = x3 split pairs (already bf16 hi/lo)
    if (tid < 32) {
        sH[tid] = g_x3h[(size_t)b * 32 + tid];
        sL[tid] = g_x3l[(size_t)b * 32 + tid];
    }
    __syncthreads();

    // ---- gather: 416 (table, quad) tasks; thread handles tasks tid, tid+256
    {
        const int t0 = tid >> 4;
        const int q  = tid & 15;
        const int t1 = t0 + 16;
        const bool has1 = (t1 < NTAB);

        const float* tab0 = emb + (size_t)t0 * VOCAB * EMBD + q * 4;
        const float* tab1 = emb + (size_t)t1 * VOCAB * EMBD + q * 4;

        float4 a0 = make_float4(0.f, 0.f, 0.f, 0.f);
        float4 a1 = make_float4(0.f, 0.f, 0.f, 0.f);

        int i0f = s_idx[t0];
        int i1f = has1 ? s_idx[t1] : 0;

        if (i0f >= 0 && i1f >= 0) {
            if (has1) {
                float4 v0 = *reinterpret_cast<const float4*>(tab0 + (size_t)i0f * EMBD);
                float4 v1 = *reinterpret_cast<const float4*>(tab1 + (size_t)i1f * EMBD);
                a0 = v0; a1 = v1;
            } else {
                a0 = *reinterpret_cast<const float4*>(tab0 + (size_t)i0f * EMBD);
            }
        } else {
            int p0 = s_beg[t0], e0 = p0 + s_len[t0];
            int p1 = has1 ? s_beg[t1] : 0;
            int e1 = has1 ? (p1 + s_len[t1]) : 0;
            while (p0 < e0 || p1 < e1) {
                int i0 = (p0 < e0) ? __ldg(lS_i + t0 * BATCH + p0) : -1;
                int i1 = (p1 < e1) ? __ldg(lS_i + t1 * BATCH + p1) : -1;
                if (i0 >= 0) {
                    float4 v = *reinterpret_cast<const float4*>(tab0 + (size_t)i0 * EMBD);
                    a0.x += v.x; a0.y += v.y; a0.z += v.z; a0.w += v.w;
                    p0++;
                }
                if (i1 >= 0) {
                    float4 v = *reinterpret_cast<const float4*>(tab1 + (size_t)i1 * EMBD);
                    a1.x += v.x; a1.y += v.y; a1.z += v.z; a1.w += v.w;
                    p1++;
                }
            }
        }

        {
            float hx = bf16_round(a0.x), hy = bf16_round(a0.y);
            float hz = bf16_round(a0.z), hw = bf16_round(a0.w);
            int base = (t0 + 1) * SROW + q * 2;
            sH[base]     = pack_bf16x2(hx, hy);
            sL[base]     = pack_bf16x2(a0.x - hx, a0.y - hy);
            sH[base + 1] = pack_bf16x2(hz, hw);
            sL[base + 1] = pack_bf16x2(a0.z - hz, a0.w - hw);
        }
        if (has1) {
            float hx = bf16_round(a1.x), hy = bf16_round(a1.y);
            float hz = bf16_round(a1.z), hw = bf16_round(a1.w);
            int base = (t1 + 1) * SROW + q * 2;
            sH[base]     = pack_bf16x2(hx, hy);
            sL[base]     = pack_bf16x2(a1.x - hx, a1.y - hy);
            sH[base + 1] = pack_bf16x2(hz, hw);
            sL[base + 1] = pack_bf16x2(a1.z - hz, a1.w - hw);
        }
    }
    __syncthreads();

    // ---- interaction: Z = T T^T (32x32x64), 8 warps = 2(m) x 4(n)
    const int g  = lane >> 2;
    const int tg = lane & 3;
    const int wm = wid & 1;
    const int wn = wid >> 1;

    float acc[4] = {0.f, 0.f, 0.f, 0.f};
    const int r0 = wm * 16 + g;
    const int r1 = r0 + 8;
    const int nb = wn * 8 + g;

    #pragma unroll
    for (int ks = 0; ks < 4; ks++) {
        int kp = ks * 8 + tg;
        uint32_t ah[4], al[4], bh[2], bl[2];
        ah[0] = sH[r0 * SROW + kp];     al[0] = sL[r0 * SROW + kp];
        ah[1] = sH[r1 * SROW + kp];     al[1] = sL[r1 * SROW + kp];
        ah[2] = sH[r0 * SROW + kp + 4]; al[2] = sL[r0 * SROW + kp + 4];
        ah[3] = sH[r1 * SROW + kp + 4]; al[3] = sL[r1 * SROW + kp + 4];
        bh[0] = sH[nb * SROW + kp];     bl[0] = sL[nb * SROW + kp];
        bh[1] = sH[nb * SROW + kp + 4]; bl[1] = sL[nb * SROW + kp + 4];
        mma_bf16(acc, ah, bh);
        mma_bf16(acc, ah, bl);
        mma_bf16(acc, al, bh);
    }

    // stage lower triangle into smem
    {
        int row = wm * 16 + g;
        int col = wn * 8 + tg * 2;
        if (row < NT1) {
            int base = row * (row - 1) / 2;
            if (col     < row) sZ[base + col]     = acc[0];
            if (col + 1 < row) sZ[base + col + 1] = acc[1];
        }
        int row2 = row + 8;
        if (row2 < NT1) {
            int base = row2 * (row2 - 1) / 2;
            if (col     < row2) sZ[base + col]     = acc[2];
            if (col + 1 < row2) sZ[base + col + 1] = acc[3];
        }
    }
    __syncthreads();

    // write R as split pairs: pairs 0..31 = x3 pairs, 32..207 from sZ
    uint32_t* Rh = g_Rh + (size_t)b * RP;
    uint32_t* Rl = g_Rl + (size_t)b * RP;
    for (int pj = tid; pj < RP; pj += 256) {
        if (pj < 32) {
            Rh[pj] = g_x3h[(size_t)b * 32 + pj];
            Rl[pj] = g_x3l[(size_t)b * 32 + pj];
        } else {
            int e0 = 2 * pj - 64;
            float v0 = sZ[e0];
            float v1 = (e0 + 1 < NPAIR) ? sZ[e0 + 1] : 0.f;
            float h0 = bf16_round(v0), h1 = bf16_round(v1);
            Rh[pj] = pack_bf16x2(h0, h1);
            Rl[pj] = pack_bf16x2(v0 - h0, v1 - h1);
        }
    }
}

// ---------------------------------------------------------------------------
// Final layer: out[b] = sigmoid( dot(z2[b], tw2) + tb2 ). One warp per row.
// ---------------------------------------------------------------------------
__global__ __launch_bounds__(256)
void top_final(const float* __restrict__ w,
               const float* __restrict__ bias,
               float* __restrict__ out)
{
    int gwarp = (blockIdx.x * blockDim.x + threadIdx.x) >> 5;
    int lane  = threadIdx.x & 31;
    if (gwarp >= BATCH) return;

    const float* z = g_z2 + (size_t)gwarp * 256;
    float s = 0.f;
    #pragma unroll
    for (int k = lane; k < 256; k += 32) s = fmaf(z[k], w[k], s);
    #pragma unroll
    for (int o = 16; o; o >>= 1) s += __shfl_xor_sync(0xFFFFFFFFu, s, o);
    if (lane == 0) out[gwarp] = 1.f / (1.f + expf(-(s + bias[0])));
}

// ---------------------------------------------------------------------------
extern "C" void kernel_launch(void* const* d_in, const int* in_sizes, int n_in,
                              void* d_out, int out_size)
{
    const float* dense_x = (const float*)d_in[0];
    const int*   lS_o    = (const int*)  d_in[1];
    const int*   lS_i    = (const int*)  d_in[2];
    const float* emb     = (const float*)d_in[3];
    const float* bb0     = (const float*)d_in[5];
    const float* bb1     = (const float*)d_in[7];
    const float* bb2     = (const float*)d_in[9];
    const float* tb0     = (const float*)d_in[11];
    const float* tb1     = (const float*)d_in[13];
    const float* tw2     = (const float*)d_in[14];
    const float* tb2     = (const float*)d_in[15];
    const float* bw0     = (const float*)d_in[4];
    const float* bw1     = (const float*)d_in[6];
    const float* bw2     = (const float*)d_in[8];
    const float* tw0     = (const float*)d_in[10];
    const float* tw1     = (const float*)d_in[12];
    float* out = (float*)d_out;

    uint32_t *dxh, *dxl, *w0h, *w0l, *w1h, *w1l, *w2h, *w2l, *t0h, *t0l, *t1h, *t1l;
    uint32_t *x1h, *x1l, *x2h, *x2l, *x3h, *x3l, *Rh, *Rl, *z1h, *z1l;
    float *z2;
    cudaGetSymbolAddress((void**)&dxh, g_dxh); cudaGetSymbolAddress((void**)&dxl, g_dxl);
    cudaGetSymbolAddress((void**)&w0h, g_w0h); cudaGetSymbolAddress((void**)&w0l, g_w0l);
    cudaGetSymbolAddress((void**)&w1h, g_w1h); cudaGetSymbolAddress((void**)&w1l, g_w1l);
    cudaGetSymbolAddress((void**)&w2h, g_w2h); cudaGetSymbolAddress((void**)&w2l, g_w2l);
    cudaGetSymbolAddress((void**)&t0h, g_t0h); cudaGetSymbolAddress((void**)&t0l, g_t0l);
    cudaGetSymbolAddress((void**)&t1h, g_t1h); cudaGetSymbolAddress((void**)&t1l, g_t1l);
    cudaGetSymbolAddress((void**)&x1h, g_x1h); cudaGetSymbolAddress((void**)&x1l, g_x1l);
    cudaGetSymbolAddress((void**)&x2h, g_x2h); cudaGetSymbolAddress((void**)&x2l, g_x2l);
    cudaGetSymbolAddress((void**)&x3h, g_x3h); cudaGetSymbolAddress((void**)&x3l, g_x3l);
    cudaGetSymbolAddress((void**)&Rh,  g_Rh);  cudaGetSymbolAddress((void**)&Rl,  g_Rl);
    cudaGetSymbolAddress((void**)&z1h, g_z1h); cudaGetSymbolAddress((void**)&z1l, g_z1l);
    cudaGetSymbolAddress((void**)&z2,  g_z2);

    // 0) split inputs/weights to bf16 hi/lo pairs
    split_all<<<(278016 + 255) / 256, 256>>>(dense_x, bw0, bw1, bw2, tw0, tw1);

    // 1) bottom MLP
    gemm_nt_mma<128, 128, 2, 4, true><<<dim3(4, 32), 256>>>(
        dxh, dxl, w0h, w0l, bb0, x1h, x1l, nullptr, 7, 7, 7, 256);
    gemm_nt_mma<64, 128, 2, 4, true><<<dim3(2, 64), 256>>>(
        x1h, x1l, w1h, w1l, bb1, x2h, x2l, nullptr, 256, 256, 256, 128);
    gemm_nt_mma<64, 64, 4, 2, true><<<dim3(1, 64), 256>>>(
        x2h, x2l, w2h, w2l, bb2, x3h, x3l, nullptr, 128, 128, 128, 32);

    // 2) fused gather + interaction -> R (split pairs)
    gather_interact<<<BATCH, 256>>>(lS_o, lS_i, emb);

    // 3) top MLP
    gemm_nt_mma<128, 128, 2, 4, true><<<dim3(4, 32), 256>>>(
        Rh, Rl, t0h, t0l, tb0, z1h, z1l, nullptr, RP, RP, RP, 256);
    gemm_nt_mma<64, 128, 2, 4, false><<<dim3(2, 64), 256>>>(
        z1h, z1l, t1h, t1l, tb1, nullptr, nullptr, z2, 256, 256, 256, 256);
    top_final<<<(BATCH * 32 + 255) / 256, 256>>>(tw2, tb2, out);
}

// round 10
// speedup vs baseline: 3.4980x; 1.0658x over previous
#include <cuda_runtime.h>
#include <cuda_bf16.h>
#include <math.h>
#include <stdint.h>

#define BATCH 4096
#define NTAB 26
#define VOCAB 100000
#define EMBD 64
#define NT1 27
#define NPAIR 351
#define RDIM 415
#define RP 208            // pairs per R row
#define SROW 36           // interact smem row stride (u32)
#define SROWG 20          // gemm smem row stride (u32): 16 pairs + 4 pad (80B, 16B-aligned rows)

// ---- pre-split weight / input buffers (hi/lo bf16x2 pairs) ----
__device__ uint32_t g_dxh[BATCH * 8],  g_dxl[BATCH * 8];   // stride 8 (pair 7 = zero pad)
__device__ uint32_t g_w0h[512 * 8],    g_w0l[512 * 8];
__device__ uint32_t g_w1h[256 * 256],  g_w1l[256 * 256];
__device__ uint32_t g_w2h[64 * 128],   g_w2l[64 * 128];
__device__ uint32_t g_t0h[512 * 208],  g_t0l[512 * 208];
__device__ uint32_t g_t1h[256 * 256],  g_t1l[256 * 256];
// ---- split activations ----
__device__ uint32_t g_x1h[BATCH * 256], g_x1l[BATCH * 256];
__device__ uint32_t g_x2h[BATCH * 128], g_x2l[BATCH * 128];
__device__ uint32_t g_x3h[BATCH * 32],  g_x3l[BATCH * 32];
__device__ uint32_t g_Rh [BATCH * RP],  g_Rl [BATCH * RP];
__device__ uint32_t g_z1h[BATCH * 256], g_z1l[BATCH * 256];
__device__ float    g_z2 [BATCH * 256];

__device__ __forceinline__ uint32_t pack_bf16x2(float lo, float hi)
{
    __nv_bfloat162 p = __floats2bfloat162_rn(lo, hi);
    return *reinterpret_cast<uint32_t*>(&p);
}
__device__ __forceinline__ float bf16_round(float v)
{
    return __bfloat162float(__float2bfloat16(v));
}
__device__ __forceinline__ void mma_bf16(float* c, const uint32_t* a, const uint32_t* b)
{
    asm volatile(
        "mma.sync.aligned.m16n8k16.row.col.f32.bf16.bf16.f32 "
        "{%0,%1,%2,%3}, {%4,%5,%6,%7}, {%8,%9}, {%0,%1,%2,%3};"
        : "+f"(c[0]), "+f"(c[1]), "+f"(c[2]), "+f"(c[3])
        : "r"(a[0]), "r"(a[1]), "r"(a[2]), "r"(a[3]), "r"(b[0]), "r"(b[1]));
}
__device__ __forceinline__ void ldm_x4(uint32_t* r, const uint32_t* p)
{
    uint32_t a = (uint32_t)__cvta_generic_to_shared(p);
    asm volatile("ldmatrix.sync.aligned.m8n8.x4.shared.b16 {%0,%1,%2,%3}, [%4];"
        : "=r"(r[0]), "=r"(r[1]), "=r"(r[2]), "=r"(r[3]) : "r"(a));
}
__device__ __forceinline__ void cp16(const uint32_t* dst, const uint32_t* src, int bytes)
{
    uint32_t d = (uint32_t)__cvta_generic_to_shared(dst);
    asm volatile("cp.async.cg.shared.global [%0], [%1], 16, %2;\n"
                 :: "r"(d), "l"(src), "r"(bytes));
}
__device__ __forceinline__ void cp_commit() { asm volatile("cp.async.commit_group;\n"); }
__device__ __forceinline__ void cp_wait_all() { asm volatile("cp.async.wait_group 0;\n"); }

// ---------------------------------------------------------------------------
// Split dense_x + 5 weight matrices into bf16 hi/lo pair arrays (padded strides).
// ---------------------------------------------------------------------------
__global__ __launch_bounds__(256)
void split_all(const float* __restrict__ dx, const float* __restrict__ w0,
               const float* __restrict__ w1, const float* __restrict__ w2,
               const float* __restrict__ t0, const float* __restrict__ t1)
{
    int i = blockIdx.x * 256 + threadIdx.x;
    if (i >= 282624) return;
    const float* src; uint32_t *dh, *dl; int K, P, local;
    if (i < 32768)       { src = dx; dh = g_dxh; dl = g_dxl; K = 13;  P = 8;   local = i; }
    else if (i < 36864)  { src = w0; dh = g_w0h; dl = g_w0l; K = 13;  P = 8;   local = i - 32768; }
    else if (i < 102400) { src = w1; dh = g_w1h; dl = g_w1l; K = 512; P = 256; local = i - 36864; }
    else if (i < 110592) { src = w2; dh = g_w2h; dl = g_w2l; K = 256; P = 128; local = i - 102400; }
    else if (i < 217088) { src = t0; dh = g_t0h; dl = g_t0l; K = 415; P = 208; local = i - 110592; }
    else                 { src = t1; dh = g_t1h; dl = g_t1l; K = 512; P = 256; local = i - 217088; }
    int row = local / P, p = local - row * P, k = 2 * p;
    float v0 = (k     < K) ? src[(size_t)row * K + k]     : 0.f;
    float v1 = (k + 1 < K) ? src[(size_t)row * K + k + 1] : 0.f;
    float h0 = bf16_round(v0), h1 = bf16_round(v1);
    dh[local] = pack_bf16x2(h0, h1);
    dl[local] = pack_bf16x2(v0 - h0, v1 - h1);
}

// ---------------------------------------------------------------------------
// NT GEMM, pre-split inputs, cp.async double-buffered: C = relu(A @ W^T + b).
// 3-pass hh+hl+lh fp32 accumulation. BK=32 (16 pairs/stage).
// One cp.async.wait + one __syncthreads per stage; loads overlap MMA.
// ldap/ldwp are PADDED pair strides (multiples of 4); Kp = real pairs.
// ---------------------------------------------------------------------------
template<int BM, int BN, int WM_, int WN_, bool SPLIT_OUT>
__global__ __launch_bounds__(256)
void gemm_nt_mma(const uint32_t* __restrict__ Ah, const uint32_t* __restrict__ Al,
                 const uint32_t* __restrict__ Wh, const uint32_t* __restrict__ Wl,
                 const float* __restrict__ bias,
                 uint32_t* __restrict__ Ch, uint32_t* __restrict__ Cl,
                 float* __restrict__ Cf,
                 int Kp, int ldap, int ldwp, int ldc)
{
    constexpr int TM  = BM / WM_;
    constexpr int TN  = BN / WN_;
    constexpr int MT  = TM / 16;
    constexpr int NTT = TN / 8;
    constexpr int NT2 = NTT / 2;
    constexpr int STG = BM * SROWG;   // one A stage (u32)
    constexpr int STGW = BN * SROWG;

    extern __shared__ __align__(16) uint32_t dyn[];
    uint32_t* sHA = dyn;                    // 2 stages
    uint32_t* sLA = sHA + 2 * STG;
    uint32_t* sHW = sLA + 2 * STG;
    uint32_t* sLW = sHW + 2 * STGW;

    const int tid  = threadIdx.x;
    const int lane = tid & 31;
    const int wid  = tid >> 5;
    const int wm   = wid % WM_;
    const int wn   = wid / WM_;
    const int g    = lane >> 2;
    const int tg   = lane & 3;
    const int bm   = blockIdx.y * BM;
    const int bn   = blockIdx.x * BN;

    const int sub_r  = lane & 7;
    const int quad   = lane >> 3;
    const int lm_row = sub_r + (quad & 1) * 8;
    const int lm_col = (quad >> 1) * 4;

    float acc[MT][NTT][4];
    #pragma unroll
    for (int i = 0; i < MT; i++)
        #pragma unroll
        for (int j = 0; j < NTT; j++)
            #pragma unroll
            for (int q = 0; q < 4; q++) acc[i][j][q] = 0.f;

    const int ntiles = (Kp + 15) / 16;

    // stage loader: chunk = 16B = 4 pairs
    auto load_stage = [&](int t, int s) {
        uint32_t* dHA = sHA + s * STG;
        uint32_t* dLA = sLA + s * STG;
        uint32_t* dHW = sHW + s * STGW;
        uint32_t* dLW = sLW + s * STGW;
        #pragma unroll
        for (int i = tid; i < BM * 4; i += 256) {
            int row = i >> 2, c = i & 3;
            int gp = t * 16 + c * 4;
            int avail = (ldap - gp) * 4;
            avail = avail < 0 ? 0 : (avail > 16 ? 16 : avail);
            int gpc = gp < ldap - 4 ? gp : ldap - 4;
            size_t goff = (size_t)(bm + row) * ldap + gpc;
            cp16(dHA + row * SROWG + c * 4, Ah + goff, avail);
            cp16(dLA + row * SROWG + c * 4, Al + goff, avail);
        }
        #pragma unroll
        for (int i = tid; i < BN * 4; i += 256) {
            int row = i >> 2, c = i & 3;
            int gp = t * 16 + c * 4;
            int avail = (ldwp - gp) * 4;
            avail = avail < 0 ? 0 : (avail > 16 ? 16 : avail);
            int gpc = gp < ldwp - 4 ? gp : ldwp - 4;
            size_t goff = (size_t)(bn + row) * ldwp + gpc;
            cp16(dHW + row * SROWG + c * 4, Wh + goff, avail);
            cp16(dLW + row * SROWG + c * 4, Wl + goff, avail);
        }
        cp_commit();
    };

    load_stage(0, 0);

    for (int t = 0; t < ntiles; t++) {
        cp_wait_all();
        __syncthreads();
        if (t + 1 < ntiles) load_stage(t + 1, (t + 1) & 1);

        const int s = t & 1;
        const uint32_t* bHA = sHA + s * STG;
        const uint32_t* bLA = sLA + s * STG;
        const uint32_t* bHW = sHW + s * STGW;
        const uint32_t* bLW = sLW + s * STGW;

        #pragma unroll
        for (int ks = 0; ks < 2; ks++) {
            const int cb = ks * 8;
            uint32_t ah[MT][4], al[MT][4], bh[NTT][2], bl[NTT][2];
            #pragma unroll
            for (int mt = 0; mt < MT; mt++) {
                int base = (wm * TM + mt * 16 + lm_row) * SROWG + cb + lm_col;
                ldm_x4(ah[mt], &bHA[base]);
                ldm_x4(al[mt], &bLA[base]);
            }
            #pragma unroll
            for (int n2 = 0; n2 < NT2; n2++) {
                int base = (wn * TN + n2 * 16 + lm_row) * SROWG + cb + lm_col;
                uint32_t q[4];
                ldm_x4(q, &bHW[base]);
                bh[2 * n2][0] = q[0]; bh[2 * n2 + 1][0] = q[1];
                bh[2 * n2][1] = q[2]; bh[2 * n2 + 1][1] = q[3];
                ldm_x4(q, &bLW[base]);
                bl[2 * n2][0] = q[0]; bl[2 * n2 + 1][0] = q[1];
                bl[2 * n2][1] = q[2]; bl[2 * n2 + 1][1] = q[3];
            }
            #pragma unroll
            for (int mt = 0; mt < MT; mt++)
                #pragma unroll
                for (int nt = 0; nt < NTT; nt++) {
                    mma_bf16(acc[mt][nt], ah[mt], bh[nt]);
                    mma_bf16(acc[mt][nt], ah[mt], bl[nt]);
                    mma_bf16(acc[mt][nt], al[mt], bh[nt]);
                }
        }
    }

    // epilogue
    #pragma unroll
    for (int mt = 0; mt < MT; mt++) {
        int r0 = bm + wm * TM + mt * 16 + g;
        #pragma unroll
        for (int nt = 0; nt < NTT; nt++) {
            int col = bn + wn * TN + nt * 8 + tg * 2;
            float bi0 = bias[col], bi1 = bias[col + 1];
            float v0 = fmaxf(acc[mt][nt][0] + bi0, 0.f);
            float v1 = fmaxf(acc[mt][nt][1] + bi1, 0.f);
            float v2 = fmaxf(acc[mt][nt][2] + bi0, 0.f);
            float v3 = fmaxf(acc[mt][nt][3] + bi1, 0.f);
            if (SPLIT_OUT) {
                int pj = col >> 1;
                float h0 = bf16_round(v0), h1 = bf16_round(v1);
                Ch[(size_t)r0 * ldc + pj] = pack_bf16x2(h0, h1);
                Cl[(size_t)r0 * ldc + pj] = pack_bf16x2(v0 - h0, v1 - h1);
                float h2 = bf16_round(v2), h3 = bf16_round(v3);
                Ch[(size_t)(r0 + 8) * ldc + pj] = pack_bf16x2(h2, h3);
                Cl[(size_t)(r0 + 8) * ldc + pj] = pack_bf16x2(v2 - h2, v3 - h3);
            } else {
                Cf[(size_t)r0 * ldc + col]           = v0;
                Cf[(size_t)r0 * ldc + col + 1]       = v1;
                Cf[(size_t)(r0 + 8) * ldc + col]     = v2;
                Cf[(size_t)(r0 + 8) * ldc + col + 1] = v3;
            }
        }
    }
}

// ---------------------------------------------------------------------------
// Fused embedding-gather + interaction (split-pair I/O).
// ---------------------------------------------------------------------------
__global__ __launch_bounds__(256)
void gather_interact(const int* __restrict__ lS_o,
                     const int* __restrict__ lS_i,
                     const float* __restrict__ emb)
{
    __shared__ uint32_t sH[32 * SROW];
    __shared__ uint32_t sL[32 * SROW];
    __shared__ float    sZ[NPAIR];
    __shared__ int s_beg[NTAB];
    __shared__ int s_len[NTAB];
    __shared__ int s_idx[NTAB];

    const int b    = blockIdx.x;
    const int tid  = threadIdx.x;
    const int lane = tid & 31;
    const int wid  = tid >> 5;

    if (tid < NTAB) {
        int beg = lS_o[tid * BATCH + b];
        int end = (b + 1 < BATCH) ? lS_o[tid * BATCH + b + 1] : BATCH;
        s_beg[tid] = beg;
        s_len[tid] = end - beg;
        s_idx[tid] = (end - beg == 1) ? __ldg(lS_i + tid * BATCH + beg) : -1;
    }
    if (tid < 32) {
        sH[tid] = g_x3h[(size_t)b * 32 + tid];
        sL[tid] = g_x3l[(size_t)b * 32 + tid];
    }
    __syncthreads();

    {
        const int t0 = tid >> 4;
        const int q  = tid & 15;
        const int t1 = t0 + 16;
        const bool has1 = (t1 < NTAB);

        const float* tab0 = emb + (size_t)t0 * VOCAB * EMBD + q * 4;
        const float* tab1 = emb + (size_t)t1 * VOCAB * EMBD + q * 4;

        float4 a0 = make_float4(0.f, 0.f, 0.f, 0.f);
        float4 a1 = make_float4(0.f, 0.f, 0.f, 0.f);

        int i0f = s_idx[t0];
        int i1f = has1 ? s_idx[t1] : 0;

        if (i0f >= 0 && i1f >= 0) {
            if (has1) {
                float4 v0 = *reinterpret_cast<const float4*>(tab0 + (size_t)i0f * EMBD);
                float4 v1 = *reinterpret_cast<const float4*>(tab1 + (size_t)i1f * EMBD);
                a0 = v0; a1 = v1;
            } else {
                a0 = *reinterpret_cast<const float4*>(tab0 + (size_t)i0f * EMBD);
            }
        } else {
            int p0 = s_beg[t0], e0 = p0 + s_len[t0];
            int p1 = has1 ? s_beg[t1] : 0;
            int e1 = has1 ? (p1 + s_len[t1]) : 0;
            while (p0 < e0 || p1 < e1) {
                int i0 = (p0 < e0) ? __ldg(lS_i + t0 * BATCH + p0) : -1;
                int i1 = (p1 < e1) ? __ldg(lS_i + t1 * BATCH + p1) : -1;
                if (i0 >= 0) {
                    float4 v = *reinterpret_cast<const float4*>(tab0 + (size_t)i0 * EMBD);
                    a0.x += v.x; a0.y += v.y; a0.z += v.z; a0.w += v.w;
                    p0++;
                }
                if (i1 >= 0) {
                    float4 v = *reinterpret_cast<const float4*>(tab1 + (size_t)i1 * EMBD);
                    a1.x += v.x; a1.y += v.y; a1.z += v.z; a1.w += v.w;
                    p1++;
                }
            }
        }

        {
            float hx = bf16_round(a0.x), hy = bf16_round(a0.y);
            float hz = bf16_round(a0.z), hw = bf16_round(a0.w);
            int base = (t0 + 1) * SROW + q * 2;
            sH[base]     = pack_bf16x2(hx, hy);
            sL[base]     = pack_bf16x2(a0.x - hx, a0.y - hy);
            sH[base + 1] = pack_bf16x2(hz, hw);
            sL[base + 1] = pack_bf16x2(a0.z - hz, a0.w - hw);
        }
        if (has1) {
            float hx = bf16_round(a1.x), hy = bf16_round(a1.y);
            float hz = bf16_round(a1.z), hw = bf16_round(a1.w);
            int base = (t1 + 1) * SROW + q * 2;
            sH[base]     = pack_bf16x2(hx, hy);
            sL[base]     = pack_bf16x2(a1.x - hx, a1.y - hy);
            sH[base + 1] = pack_bf16x2(hz, hw);
            sL[base + 1] = pack_bf16x2(a1.z - hz, a1.w - hw);
        }
    }
    __syncthreads();

    const int g  = lane >> 2;
    const int tg = lane & 3;
    const int wm = wid & 1;
    const int wn = wid >> 1;

    float acc[4] = {0.f, 0.f, 0.f, 0.f};
    const int r0 = wm * 16 + g;
    const int r1 = r0 + 8;
    const int nb = wn * 8 + g;

    #pragma unroll
    for (int ks = 0; ks < 4; ks++) {
        int kp = ks * 8 + tg;
        uint32_t ah[4], al[4], bh[2], bl[2];
        ah[0] = sH[r0 * SROW + kp];     al[0] = sL[r0 * SROW + kp];
        ah[1] = sH[r1 * SROW + kp];     al[1] = sL[r1 * SROW + kp];
        ah[2] = sH[r0 * SROW + kp + 4]; al[2] = sL[r0 * SROW + kp + 4];
        ah[3] = sH[r1 * SROW + kp + 4]; al[3] = sL[r1 * SROW + kp + 4];
        bh[0] = sH[nb * SROW + kp];     bl[0] = sL[nb * SROW + kp];
        bh[1] = sH[nb * SROW + kp + 4]; bl[1] = sL[nb * SROW + kp + 4];
        mma_bf16(acc, ah, bh);
        mma_bf16(acc, ah, bl);
        mma_bf16(acc, al, bh);
    }

    {
        int row = wm * 16 + g;
        int col = wn * 8 + tg * 2;
        if (row < NT1) {
            int base = row * (row - 1) / 2;
            if (col     < row) sZ[base + col]     = acc[0];
            if (col + 1 < row) sZ[base + col + 1] = acc[1];
        }
        int row2 = row + 8;
        if (row2 < NT1) {
            int base = row2 * (row2 - 1) / 2;
            if (col     < row2) sZ[base + col]     = acc[2];
            if (col + 1 < row2) sZ[base + col + 1] = acc[3];
        }
    }
    __syncthreads();

    uint32_t* Rh = g_Rh + (size_t)b * RP;
    uint32_t* Rl = g_Rl + (size_t)b * RP;
    for (int pj = tid; pj < RP; pj += 256) {
        if (pj < 32) {
            Rh[pj] = g_x3h[(size_t)b * 32 + pj];
            Rl[pj] = g_x3l[(size_t)b * 32 + pj];
        } else {
            int e0 = 2 * pj - 64;
            float v0 = sZ[e0];
            float v1 = (e0 + 1 < NPAIR) ? sZ[e0 + 1] : 0.f;
            float h0 = bf16_round(v0), h1 = bf16_round(v1);
            Rh[pj] = pack_bf16x2(h0, h1);
            Rl[pj] = pack_bf16x2(v0 - h0, v1 - h1);
        }
    }
}

// ---------------------------------------------------------------------------
__global__ __launch_bounds__(256)
void top_final(const float* __restrict__ w,
               const float* __restrict__ bias,
               float* __restrict__ out)
{
    int gwarp = (blockIdx.x * blockDim.x + threadIdx.x) >> 5;
    int lane  = threadIdx.x & 31;
    if (gwarp >= BATCH) return;

    const float* z = g_z2 + (size_t)gwarp * 256;
    float s = 0.f;
    #pragma unroll
    for (int k = lane; k < 256; k += 32) s = fmaf(z[k], w[k], s);
    #pragma unroll
    for (int o = 16; o; o >>= 1) s += __shfl_xor_sync(0xFFFFFFFFu, s, o);
    if (lane == 0) out[gwarp] = 1.f / (1.f + expf(-(s + bias[0])));
}

// ---------------------------------------------------------------------------
static inline int smem_bytes(int BM, int BN) { return (4 * BM + 4 * BN) * SROWG * 4; }

extern "C" void kernel_launch(void* const* d_in, const int* in_sizes, int n_in,
                              void* d_out, int out_size)
{
    const float* dense_x = (const float*)d_in[0];
    const int*   lS_o    = (const int*)  d_in[1];
    const int*   lS_i    = (const int*)  d_in[2];
    const float* emb     = (const float*)d_in[3];
    const float* bw0     = (const float*)d_in[4];
    const float* bb0     = (const float*)d_in[5];
    const float* bw1     = (const float*)d_in[6];
    const float* bb1     = (const float*)d_in[7];
    const float* bw2     = (const float*)d_in[8];
    const float* bb2     = (const float*)d_in[9];
    const float* tw0     = (const float*)d_in[10];
    const float* tb0     = (const float*)d_in[11];
    const float* tw1     = (const float*)d_in[12];
    const float* tb1     = (const float*)d_in[13];
    const float* tw2     = (const float*)d_in[14];
    const float* tb2     = (const float*)d_in[15];
    float* out = (float*)d_out;

    uint32_t *dxh, *dxl, *w0h, *w0l, *w1h, *w1l, *w2h, *w2l, *t0h, *t0l, *t1h, *t1l;
    uint32_t *x1h, *x1l, *x2h, *x2l, *x3h, *x3l, *Rh, *Rl, *z1h, *z1l;
    float *z2;
    cudaGetSymbolAddress((void**)&dxh, g_dxh); cudaGetSymbolAddress((void**)&dxl, g_dxl);
    cudaGetSymbolAddress((void**)&w0h, g_w0h); cudaGetSymbolAddress((void**)&w0l, g_w0l);
    cudaGetSymbolAddress((void**)&w1h, g_w1h); cudaGetSymbolAddress((void**)&w1l, g_w1l);
    cudaGetSymbolAddress((void**)&w2h, g_w2h); cudaGetSymbolAddress((void**)&w2l, g_w2l);
    cudaGetSymbolAddress((void**)&t0h, g_t0h); cudaGetSymbolAddress((void**)&t0l, g_t0l);
    cudaGetSymbolAddress((void**)&t1h, g_t1h); cudaGetSymbolAddress((void**)&t1l, g_t1l);
    cudaGetSymbolAddress((void**)&x1h, g_x1h); cudaGetSymbolAddress((void**)&x1l, g_x1l);
    cudaGetSymbolAddress((void**)&x2h, g_x2h); cudaGetSymbolAddress((void**)&x2l, g_x2l);
    cudaGetSymbolAddress((void**)&x3h, g_x3h); cudaGetSymbolAddress((void**)&x3l, g_x3l);
    cudaGetSymbolAddress((void**)&Rh,  g_Rh);  cudaGetSymbolAddress((void**)&Rl,  g_Rl);
    cudaGetSymbolAddress((void**)&z1h, g_z1h); cudaGetSymbolAddress((void**)&z1l, g_z1l);
    cudaGetSymbolAddress((void**)&z2,  g_z2);

    // raise dynamic smem limits (idempotent)
    cudaFuncSetAttribute(gemm_nt_mma<128, 128, 2, 4, true>,
                         cudaFuncAttributeMaxDynamicSharedMemorySize, smem_bytes(128, 128));
    cudaFuncSetAttribute(gemm_nt_mma<64, 128, 2, 4, true>,
                         cudaFuncAttributeMaxDynamicSharedMemorySize, smem_bytes(64, 128));
    cudaFuncSetAttribute(gemm_nt_mma<64, 128, 2, 4, false>,
                         cudaFuncAttributeMaxDynamicSharedMemorySize, smem_bytes(64, 128));
    cudaFuncSetAttribute(gemm_nt_mma<32, 64, 2, 4, true>,
                         cudaFuncAttributeMaxDynamicSharedMemorySize, smem_bytes(32, 64));

    // 0) split inputs/weights
    split_all<<<(282624 + 255) / 256, 256>>>(dense_x, bw0, bw1, bw2, tw0, tw1);

    // 1) bottom MLP
    gemm_nt_mma<128, 128, 2, 4, true><<<dim3(4, 32), 256, smem_bytes(128, 128)>>>(
        dxh, dxl, w0h, w0l, bb0, x1h, x1l, nullptr, 7, 8, 8, 256);
    gemm_nt_mma<64, 128, 2, 4, true><<<dim3(2, 64), 256, smem_bytes(64, 128)>>>(
        x1h, x1l, w1h, w1l, bb1, x2h, x2l, nullptr, 256, 256, 256, 128);
    gemm_nt_mma<32, 64, 2, 4, true><<<dim3(1, 128), 256, smem_bytes(32, 64)>>>(
        x2h, x2l, w2h, w2l, bb2, x3h, x3l, nullptr, 128, 128, 128, 32);

    // 2) fused gather + interaction -> R (split pairs)
    gather_interact<<<BATCH, 256>>>(lS_o, lS_i, emb);

    // 3) top MLP
    gemm_nt_mma<128, 128, 2, 4, true><<<dim3(4, 32), 256, smem_bytes(128, 128)>>>(
        Rh, Rl, t0h, t0l, tb0, z1h, z1l, nullptr, RP, RP, RP, 256);
    gemm_nt_mma<64, 128, 2, 4, false><<<dim3(2, 64), 256, smem_bytes(64, 128)>>>(
        z1h, z1l, t1h, t1l, tb1, nullptr, nullptr, z2, 256, 256, 256, 256);
    top_final<<<(BATCH * 32 + 255) / 256, 256>>>(tw2, tb2, out);
}

// round 12
// speedup vs baseline: 3.5749x; 1.0220x over previous
#include <cuda_runtime.h>
#include <cuda_bf16.h>
#include <math.h>
#include <stdint.h>

#define BATCH 4096
#define NTAB 26
#define VOCAB 100000
#define EMBD 64
#define NT1 27
#define NPAIR 351
#define RDIM 415
#define RP 208            // pairs per R row
#define SROW 36           // interact smem row stride (u32)
#define SROWG 20          // gemm smem row stride (u32): 16 pairs + 4 pad

// ---- pre-split weight / input buffers (hi/lo bf16x2 pairs) ----
__device__ uint32_t g_dxh[BATCH * 8],  g_dxl[BATCH * 8];
__device__ uint32_t g_w0h[512 * 8],    g_w0l[512 * 8];
__device__ uint32_t g_w1h[256 * 256],  g_w1l[256 * 256];
__device__ uint32_t g_w2h[64 * 128],   g_w2l[64 * 128];
__device__ uint32_t g_t0h[512 * 208],  g_t0l[512 * 208];
__device__ uint32_t g_t1h[256 * 256],  g_t1l[256 * 256];
// ---- split activations ----
__device__ uint32_t g_x1h[BATCH * 256], g_x1l[BATCH * 256];
__device__ uint32_t g_x2h[BATCH * 128], g_x2l[BATCH * 128];
__device__ uint32_t g_x3h[BATCH * 32],  g_x3l[BATCH * 32];
__device__ uint32_t g_Rh [BATCH * RP],  g_Rl [BATCH * RP];
__device__ uint32_t g_z1h[BATCH * 256], g_z1l[BATCH * 256];
__device__ float    g_z2 [BATCH * 256];

__device__ __forceinline__ uint32_t pack_bf16x2(float lo, float hi)
{
    __nv_bfloat162 p = __floats2bfloat162_rn(lo, hi);
    return *reinterpret_cast<uint32_t*>(&p);
}
__device__ __forceinline__ float bf16_round(float v)
{
    return __bfloat162float(__float2bfloat16(v));
}
__device__ __forceinline__ void mma_bf16(float* c, const uint32_t* a, const uint32_t* b)
{
    asm volatile(
        "mma.sync.aligned.m16n8k16.row.col.f32.bf16.bf16.f32 "
        "{%0,%1,%2,%3}, {%4,%5,%6,%7}, {%8,%9}, {%0,%1,%2,%3};"
        : "+f"(c[0]), "+f"(c[1]), "+f"(c[2]), "+f"(c[3])
        : "r"(a[0]), "r"(a[1]), "r"(a[2]), "r"(a[3]), "r"(b[0]), "r"(b[1]));
}
__device__ __forceinline__ void ldm_x4(uint32_t* r, const uint32_t* p)
{
    uint32_t a = (uint32_t)__cvta_generic_to_shared(p);
    asm volatile("ldmatrix.sync.aligned.m8n8.x4.shared.b16 {%0,%1,%2,%3}, [%4];"
        : "=r"(r[0]), "=r"(r[1]), "=r"(r[2]), "=r"(r[3]) : "r"(a));
}
__device__ __forceinline__ void cp16(const uint32_t* dst, const uint32_t* src, int bytes)
{
    uint32_t d = (uint32_t)__cvta_generic_to_shared(dst);
    asm volatile("cp.async.cg.shared.global [%0], [%1], 16, %2;\n"
                 :: "r"(d), "l"(src), "r"(bytes));
}
__device__ __forceinline__ void cp_commit() { asm volatile("cp.async.commit_group;\n"); }
template<int N>
__device__ __forceinline__ void cp_wait() { asm volatile("cp.async.wait_group %0;\n" :: "n"(N)); }

// ---------------------------------------------------------------------------
// Split dense_x + 5 weight matrices into bf16 hi/lo pair arrays (padded strides).
// ---------------------------------------------------------------------------
__global__ __launch_bounds__(256)
void split_all(const float* __restrict__ dx, const float* __restrict__ w0,
               const float* __restrict__ w1, const float* __restrict__ w2,
               const float* __restrict__ t0, const float* __restrict__ t1)
{
    int i = blockIdx.x * 256 + threadIdx.x;
    if (i >= 282624) return;
    const float* src; uint32_t *dh, *dl; int K, P, local;
    if (i < 32768)       { src = dx; dh = g_dxh; dl = g_dxl; K = 13;  P = 8;   local = i; }
    else if (i < 36864)  { src = w0; dh = g_w0h; dl = g_w0l; K = 13;  P = 8;   local = i - 32768; }
    else if (i < 102400) { src = w1; dh = g_w1h; dl = g_w1l; K = 512; P = 256; local = i - 36864; }
    else if (i < 110592) { src = w2; dh = g_w2h; dl = g_w2l; K = 256; P = 128; local = i - 102400; }
    else if (i < 217088) { src = t0; dh = g_t0h; dl = g_t0l; K = 415; P = 208; local = i - 110592; }
    else                 { src = t1; dh = g_t1h; dl = g_t1l; K = 512; P = 256; local = i - 217088; }
    int row = local / P, p = local - row * P, k = 2 * p;
    float v0 = (k     < K) ? src[(size_t)row * K + k]     : 0.f;
    float v1 = (k + 1 < K) ? src[(size_t)row * K + k + 1] : 0.f;
    float h0 = bf16_round(v0), h1 = bf16_round(v1);
    dh[local] = pack_bf16x2(h0, h1);
    dl[local] = pack_bf16x2(v0 - h0, v1 - h1);
}

// ---------------------------------------------------------------------------
// NT GEMM, pre-split inputs, STAGES-deep cp.async pipeline:
// C = relu(A @ W^T + bias). 3-pass hh+hl+lh fp32 acc. BK=32 (16 pairs/stage).
// Loads issued STAGES-1 tiles ahead -> per-tile load latency hidden even at
// 1 block/SM. ldap/ldwp padded pair strides (mult of 4); Kp = real pairs.
// ---------------------------------------------------------------------------
template<int BM, int BN, int WM_, int WN_, bool SPLIT_OUT, int STAGES>
__global__ __launch_bounds__(256)
void gemm_nt_mma(const uint32_t* __restrict__ Ah, const uint32_t* __restrict__ Al,
                 const uint32_t* __restrict__ Wh, const uint32_t* __restrict__ Wl,
                 const float* __restrict__ bias,
                 uint32_t* __restrict__ Ch, uint32_t* __restrict__ Cl,
                 float* __restrict__ Cf,
                 int Kp, int ldap, int ldwp, int ldc)
{
    constexpr int TM  = BM / WM_;
    constexpr int TN  = BN / WN_;
    constexpr int MT  = TM / 16;
    constexpr int NTT = TN / 8;
    constexpr int NT2 = NTT / 2;
    constexpr int STG  = BM * SROWG;
    constexpr int STGW = BN * SROWG;

    extern __shared__ __align__(16) uint32_t dyn[];
    uint32_t* sHA = dyn;                        // STAGES stages each
    uint32_t* sLA = sHA + STAGES * STG;
    uint32_t* sHW = sLA + STAGES * STG;
    uint32_t* sLW = sHW + STAGES * STGW;

    const int tid  = threadIdx.x;
    const int lane = tid & 31;
    const int wid  = tid >> 5;
    const int wm   = wid % WM_;
    const int wn   = wid / WM_;
    const int g    = lane >> 2;
    const int tg   = lane & 3;
    const int bm   = blockIdx.y * BM;
    const int bn   = blockIdx.x * BN;

    const int sub_r  = lane & 7;
    const int quad   = lane >> 3;
    const int lm_row = sub_r + (quad & 1) * 8;
    const int lm_col = (quad >> 1) * 4;

    float acc[MT][NTT][4];
    #pragma unroll
    for (int i = 0; i < MT; i++)
        #pragma unroll
        for (int j = 0; j < NTT; j++)
            #pragma unroll
            for (int q = 0; q < 4; q++) acc[i][j][q] = 0.f;

    const int ntiles = (Kp + 15) / 16;

    auto load_stage = [&](int t, int s) {
        uint32_t* dHA = sHA + s * STG;
        uint32_t* dLA = sLA + s * STG;
        uint32_t* dHW = sHW + s * STGW;
        uint32_t* dLW = sLW + s * STGW;
        for (int i = tid; i < BM * 4; i += 256) {
            int row = i >> 2, c = i & 3;
            int gp = t * 16 + c * 4;
            int avail = (ldap - gp) * 4;
            avail = avail < 0 ? 0 : (avail > 16 ? 16 : avail);
            int gpc = gp < ldap - 4 ? gp : ldap - 4;
            size_t goff = (size_t)(bm + row) * ldap + gpc;
            cp16(dHA + row * SROWG + c * 4, Ah + goff, avail);
            cp16(dLA + row * SROWG + c * 4, Al + goff, avail);
        }
        for (int i = tid; i < BN * 4; i += 256) {
            int row = i >> 2, c = i & 3;
            int gp = t * 16 + c * 4;
            int avail = (ldwp - gp) * 4;
            avail = avail < 0 ? 0 : (avail > 16 ? 16 : avail);
            int gpc = gp < ldwp - 4 ? gp : ldwp - 4;
            size_t goff = (size_t)(bn + row) * ldwp + gpc;
            cp16(dHW + row * SROWG + c * 4, Wh + goff, avail);
            cp16(dLW + row * SROWG + c * 4, Wl + goff, avail);
        }
        cp_commit();
    };

    // prologue: fill STAGES-1 stages
    #pragma unroll
    for (int s = 0; s < STAGES - 1; s++) {
        if (s < ntiles) load_stage(s, s); else cp_commit();
    }

    for (int t = 0; t < ntiles; t++) {
        cp_wait<STAGES - 2>();
        __syncthreads();
        {
            int nt_ = t + STAGES - 1;
            if (nt_ < ntiles) load_stage(nt_, nt_ % STAGES); else cp_commit();
        }

        const int s = t % STAGES;
        const uint32_t* bHA = sHA + s * STG;
        const uint32_t* bLA = sLA + s * STG;
        const uint32_t* bHW = sHW + s * STGW;
        const uint32_t* bLW = sLW + s * STGW;

        #pragma unroll
        for (int ks = 0; ks < 2; ks++) {
            const int cb = ks * 8;
            uint32_t ah[MT][4], al[MT][4], bh[NTT][2], bl[NTT][2];
            #pragma unroll
            for (int mt = 0; mt < MT; mt++) {
                int base = (wm * TM + mt * 16 + lm_row) * SROWG + cb + lm_col;
                ldm_x4(ah[mt], &bHA[base]);
                ldm_x4(al[mt], &bLA[base]);
            }
            #pragma unroll
            for (int n2 = 0; n2 < NT2; n2++) {
                int base = (wn * TN + n2 * 16 + lm_row) * SROWG + cb + lm_col;
                uint32_t q[4];
                ldm_x4(q, &bHW[base]);
                bh[2 * n2][0] = q[0]; bh[2 * n2 + 1][0] = q[1];
                bh[2 * n2][1] = q[2]; bh[2 * n2 + 1][1] = q[3];
                ldm_x4(q, &bLW[base]);
                bl[2 * n2][0] = q[0]; bl[2 * n2 + 1][0] = q[1];
                bl[2 * n2][1] = q[2]; bl[2 * n2 + 1][1] = q[3];
            }
            #pragma unroll
            for (int mt = 0; mt < MT; mt++)
                #pragma unroll
                for (int nt = 0; nt < NTT; nt++) {
                    mma_bf16(acc[mt][nt], ah[mt], bh[nt]);
                    mma_bf16(acc[mt][nt], ah[mt], bl[nt]);
                    mma_bf16(acc[mt][nt], al[mt], bh[nt]);
                }
        }
        __syncthreads();
    }

    // epilogue
    #pragma unroll
    for (int mt = 0; mt < MT; mt++) {
        int r0 = bm + wm * TM + mt * 16 + g;
        #pragma unroll
        for (int nt = 0; nt < NTT; nt++) {
            int col = bn + wn * TN + nt * 8 + tg * 2;
            float bi0 = bias[col], bi1 = bias[col + 1];
            float v0 = fmaxf(acc[mt][nt][0] + bi0, 0.f);
            float v1 = fmaxf(acc[mt][nt][1] + bi1, 0.f);
            float v2 = fmaxf(acc[mt][nt][2] + bi0, 0.f);
            float v3 = fmaxf(acc[mt][nt][3] + bi1, 0.f);
            if (SPLIT_OUT) {
                int pj = col >> 1;
                float h0 = bf16_round(v0), h1 = bf16_round(v1);
                Ch[(size_t)r0 * ldc + pj] = pack_bf16x2(h0, h1);
                Cl[(size_t)r0 * ldc + pj] = pack_bf16x2(v0 - h0, v1 - h1);
                float h2 = bf16_round(v2), h3 = bf16_round(v3);
                Ch[(size_t)(r0 + 8) * ldc + pj] = pack_bf16x2(h2, h3);
                Cl[(size_t)(r0 + 8) * ldc + pj] = pack_bf16x2(v2 - h2, v3 - h3);
            } else {
                Cf[(size_t)r0 * ldc + col]           = v0;
                Cf[(size_t)r0 * ldc + col + 1]       = v1;
                Cf[(size_t)(r0 + 8) * ldc + col]     = v2;
                Cf[(size_t)(r0 + 8) * ldc + col + 1] = v3;
            }
        }
    }
}

// ---------------------------------------------------------------------------
// Fused embedding-gather + interaction (split-pair I/O).
// ---------------------------------------------------------------------------
__global__ __launch_bounds__(256)
void gather_interact(const int* __restrict__ lS_o,
                     const int* __restrict__ lS_i,
                     const float* __restrict__ emb)
{
    __shared__ uint32_t sH[32 * SROW];
    __shared__ uint32_t sL[32 * SROW];
    __shared__ float    sZ[NPAIR];
    __shared__ int s_beg[NTAB];
    __shared__ int s_len[NTAB];
    __shared__ int s_idx[NTAB];

    const int b    = blockIdx.x;
    const int tid  = threadIdx.x;
    const int lane = tid & 31;
    const int wid  = tid >> 5;

    if (tid < NTAB) {
        int beg = lS_o[tid * BATCH + b];
        int end = (b + 1 < BATCH) ? lS_o[tid * BATCH + b + 1] : BATCH;
        s_beg[tid] = beg;
        s_len[tid] = end - beg;
        s_idx[tid] = (end - beg == 1) ? __ldg(lS_i + tid * BATCH + beg) : -1;
    }
    if (tid < 32) {
        sH[tid] = g_x3h[(size_t)b * 32 + tid];
        sL[tid] = g_x3l[(size_t)b * 32 + tid];
    }
    __syncthreads();

    {
        const int t0 = tid >> 4;
        const int q  = tid & 15;
        const int t1 = t0 + 16;
        const bool has1 = (t1 < NTAB);

        const float* tab0 = emb + (size_t)t0 * VOCAB * EMBD + q * 4;
        const float* tab1 = emb + (size_t)t1 * VOCAB * EMBD + q * 4;

        float4 a0 = make_float4(0.f, 0.f, 0.f, 0.f);
        float4 a1 = make_float4(0.f, 0.f, 0.f, 0.f);

        int i0f = s_idx[t0];
        int i1f = has1 ? s_idx[t1] : 0;

        if (i0f >= 0 && i1f >= 0) {
            if (has1) {
                float4 v0 = *reinterpret_cast<const float4*>(tab0 + (size_t)i0f * EMBD);
                float4 v1 = *reinterpret_cast<const float4*>(tab1 + (size_t)i1f * EMBD);
                a0 = v0; a1 = v1;
            } else {
                a0 = *reinterpret_cast<const float4*>(tab0 + (size_t)i0f * EMBD);
            }
        } else {
            int p0 = s_beg[t0], e0 = p0 + s_len[t0];
            int p1 = has1 ? s_beg[t1] : 0;
            int e1 = has1 ? (p1 + s_len[t1]) : 0;
            while (p0 < e0 || p1 < e1) {
                int i0 = (p0 < e0) ? __ldg(lS_i + t0 * BATCH + p0) : -1;
                int i1 = (p1 < e1) ? __ldg(lS_i + t1 * BATCH + p1) : -1;
                if (i0 >= 0) {
                    float4 v = *reinterpret_cast<const float4*>(tab0 + (size_t)i0 * EMBD);
                    a0.x += v.x; a0.y += v.y; a0.z += v.z; a0.w += v.w;
                    p0++;
                }
                if (i1 >= 0) {
                    float4 v = *reinterpret_cast<const float4*>(tab1 + (size_t)i1 * EMBD);
                    a1.x += v.x; a1.y += v.y; a1.z += v.z; a1.w += v.w;
                    p1++;
                }
            }
        }

        {
            float hx = bf16_round(a0.x), hy = bf16_round(a0.y);
            float hz = bf16_round(a0.z), hw = bf16_round(a0.w);
            int base = (t0 + 1) * SROW + q * 2;
            sH[base]     = pack_bf16x2(hx, hy);
            sL[base]     = pack_bf16x2(a0.x - hx, a0.y - hy);
            sH[base + 1] = pack_bf16x2(hz, hw);
            sL[base + 1] = pack_bf16x2(a0.z - hz, a0.w - hw);
        }
        if (has1) {
            float hx = bf16_round(a1.x), hy = bf16_round(a1.y);
            float hz = bf16_round(a1.z), hw = bf16_round(a1.w);
            int base = (t1 + 1) * SROW + q * 2;
            sH[base]     = pack_bf16x2(hx, hy);
            sL[base]     = pack_bf16x2(a1.x - hx, a1.y - hy);
            sH[base + 1] = pack_bf16x2(hz, hw);
            sL[base + 1] = pack_bf16x2(a1.z - hz, a1.w - hw);
        }
    }
    __syncthreads();

    const int g  = lane >> 2;
    const int tg = lane & 3;
    const int wm = wid & 1;
    const int wn = wid >> 1;

    float acc[4] = {0.f, 0.f, 0.f, 0.f};
    const int r0 = wm * 16 + g;
    const int r1 = r0 + 8;
    const int nb = wn * 8 + g;

    #pragma unroll
    for (int ks = 0; ks < 4; ks++) {
        int kp = ks * 8 + tg;
        uint32_t ah[4], al[4], bh[2], bl[2];
        ah[0] = sH[r0 * SROW + kp];     al[0] = sL[r0 * SROW + kp];
        ah[1] = sH[r1 * SROW + kp];     al[1] = sL[r1 * SROW + kp];
        ah[2] = sH[r0 * SROW + kp + 4]; al[2] = sL[r0 * SROW + kp + 4];
        ah[3] = sH[r1 * SROW + kp + 4]; al[3] = sL[r1 * SROW + kp + 4];
        bh[0] = sH[nb * SROW + kp];     bl[0] = sL[nb * SROW + kp];
        bh[1] = sH[nb * SROW + kp + 4]; bl[1] = sL[nb * SROW + kp + 4];
        mma_bf16(acc, ah, bh);
        mma_bf16(acc, ah, bl);
        mma_bf16(acc, al, bh);
    }

    {
        int row = wm * 16 + g;
        int col = wn * 8 + tg * 2;
        if (row < NT1) {
            int base = row * (row - 1) / 2;
            if (col     < row) sZ[base + col]     = acc[0];
            if (col + 1 < row) sZ[base + col + 1] = acc[1];
        }
        int row2 = row + 8;
        if (row2 < NT1) {
            int base = row2 * (row2 - 1) / 2;
            if (col     < row2) sZ[base + col]     = acc[2];
            if (col + 1 < row2) sZ[base + col + 1] = acc[3];
        }
    }
    __syncthreads();

    uint32_t* Rh = g_Rh + (size_t)b * RP;
    uint32_t* Rl = g_Rl + (size_t)b * RP;
    for (int pj = tid; pj < RP; pj += 256) {
        if (pj < 32) {
            Rh[pj] = g_x3h[(size_t)b * 32 + pj];
            Rl[pj] = g_x3l[(size_t)b * 32 + pj];
        } else {
            int e0 = 2 * pj - 64;
            float v0 = sZ[e0];
            float v1 = (e0 + 1 < NPAIR) ? sZ[e0 + 1] : 0.f;
            float h0 = bf16_round(v0), h1 = bf16_round(v1);
            Rh[pj] = pack_bf16x2(h0, h1);
            Rl[pj] = pack_bf16x2(v0 - h0, v1 - h1);
        }
    }
}

// ---------------------------------------------------------------------------
__global__ __launch_bounds__(256)
void top_final(const float* __restrict__ w,
               const float* __restrict__ bias,
               float* __restrict__ out)
{
    int gwarp = (blockIdx.x * blockDim.x + threadIdx.x) >> 5;
    int lane  = threadIdx.x & 31;
    if (gwarp >= BATCH) return;

    const float* z = g_z2 + (size_t)gwarp * 256;
    float s = 0.f;
    #pragma unroll
    for (int k = lane; k < 256; k += 32) s = fmaf(z[k], w[k], s);
    #pragma unroll
    for (int o = 16; o; o >>= 1) s += __shfl_xor_sync(0xFFFFFFFFu, s, o);
    if (lane == 0) out[gwarp] = 1.f / (1.f + expf(-(s + bias[0])));
}

// ---------------------------------------------------------------------------
static inline int smem_bytes(int BM, int BN, int stages)
{
    return stages * (2 * BM + 2 * BN) * SROWG * 4;
}

extern "C" void kernel_launch(void* const* d_in, const int* in_sizes, int n_in,
                              void* d_out, int out_size)
{
    const float* dense_x = (const float*)d_in[0];
    const int*   lS_o    = (const int*)  d_in[1];
    const int*   lS_i    = (const int*)  d_in[2];
    const float* emb     = (const float*)d_in[3];
    const float* bw0     = (const float*)d_in[4];
    const float* bb0     = (const float*)d_in[5];
    const float* bw1     = (const float*)d_in[6];
    const float* bb1     = (const float*)d_in[7];
    const float* bw2     = (const float*)d_in[8];
    const float* bb2     = (const float*)d_in[9];
    const float* tw0     = (const float*)d_in[10];
    const float* tb0     = (const float*)d_in[11];
    const float* tw1     = (const float*)d_in[12];
    const float* tb1     = (const float*)d_in[13];
    const float* tw2     = (const float*)d_in[14];
    const float* tb2     = (const float*)d_in[15];
    float* out = (float*)d_out;

    uint32_t *dxh, *dxl, *w0h, *w0l, *w1h, *w1l, *w2h, *w2l, *t0h, *t0l, *t1h, *t1l;
    uint32_t *x1h, *x1l, *x2h, *x2l, *x3h, *x3l, *Rh, *Rl, *z1h, *z1l;
    float *z2;
    cudaGetSymbolAddress((void**)&dxh, g_dxh); cudaGetSymbolAddress((void**)&dxl, g_dxl);
    cudaGetSymbolAddress((void**)&w0h, g_w0h); cudaGetSymbolAddress((void**)&w0l, g_w0l);
    cudaGetSymbolAddress((void**)&w1h, g_w1h); cudaGetSymbolAddress((void**)&w1l, g_w1l);
    cudaGetSymbolAddress((void**)&w2h, g_w2h); cudaGetSymbolAddress((void**)&w2l, g_w2l);
    cudaGetSymbolAddress((void**)&t0h, g_t0h); cudaGetSymbolAddress((void**)&t0l, g_t0l);
    cudaGetSymbolAddress((void**)&t1h, g_t1h); cudaGetSymbolAddress((void**)&t1l, g_t1l);
    cudaGetSymbolAddress((void**)&x1h, g_x1h); cudaGetSymbolAddress((void**)&x1l, g_x1l);
    cudaGetSymbolAddress((void**)&x2h, g_x2h); cudaGetSymbolAddress((void**)&x2l, g_x2l);
    cudaGetSymbolAddress((void**)&x3h, g_x3h); cudaGetSymbolAddress((void**)&x3l, g_x3l);
    cudaGetSymbolAddress((void**)&Rh,  g_Rh);  cudaGetSymbolAddress((void**)&Rl,  g_Rl);
    cudaGetSymbolAddress((void**)&z1h, g_z1h); cudaGetSymbolAddress((void**)&z1l, g_z1l);
    cudaGetSymbolAddress((void**)&z2,  g_z2);

    cudaFuncSetAttribute(gemm_nt_mma<128, 128, 2, 4, true, 2>,
                         cudaFuncAttributeMaxDynamicSharedMemorySize, smem_bytes(128, 128, 2));
    cudaFuncSetAttribute(gemm_nt_mma<128, 128, 2, 4, true, 4>,
                         cudaFuncAttributeMaxDynamicSharedMemorySize, smem_bytes(128, 128, 4));
    cudaFuncSetAttribute(gemm_nt_mma<64, 128, 2, 4, true, 4>,
                         cudaFuncAttributeMaxDynamicSharedMemorySize, smem_bytes(64, 128, 4));
    cudaFuncSetAttribute(gemm_nt_mma<64, 128, 2, 4, false, 4>,
                         cudaFuncAttributeMaxDynamicSharedMemorySize, smem_bytes(64, 128, 4));
    cudaFuncSetAttribute(gemm_nt_mma<32, 64, 2, 4, true, 4>,
                         cudaFuncAttributeMaxDynamicSharedMemorySize, smem_bytes(32, 64, 4));

    // 0) split inputs/weights
    split_all<<<(282624 + 255) / 256, 256>>>(dense_x, bw0, bw1, bw2, tw0, tw1);

    // 1) bottom MLP
    gemm_nt_mma<128, 128, 2, 4, true, 2><<<dim3(4, 32), 256, smem_bytes(128, 128, 2)>>>(
        dxh, dxl, w0h, w0l, bb0, x1h, x1l, nullptr, 7, 8, 8, 256);
    gemm_nt_mma<64, 128, 2, 4, true, 4><<<dim3(2, 64), 256, smem_bytes(64, 128, 4)>>>(
        x1h, x1l, w1h, w1l, bb1, x2h, x2l, nullptr, 256, 256, 256, 128);
    gemm_nt_mma<32, 64, 2, 4, true, 4><<<dim3(1, 128), 256, smem_bytes(32, 64, 4)>>>(
        x2h, x2l, w2h, w2l, bb2, x3h, x3l, nullptr, 128, 128, 128, 32);

    // 2) fused gather + interaction -> R (split pairs)
    gather_interact<<<BATCH, 256>>>(lS_o, lS_i, emb);

    // 3) top MLP
    gemm_nt_mma<128, 128, 2, 4, true, 4><<<dim3(4, 32), 256, smem_bytes(128, 128, 4)>>>(
        Rh, Rl, t0h, t0l, tb0, z1h, z1l, nullptr, RP, RP, RP, 256);
    gemm_nt_mma<64, 128, 2, 4, false, 4><<<dim3(2, 64), 256, smem_bytes(64, 128, 4)>>>(
        z1h, z1l, t1h, t1l, tb1, nullptr, nullptr, z2, 256, 256, 256, 256);
    top_final<<<(BATCH * 32 + 255) / 256, 256>>>(tw2, tb2, out);
}